// round 1
// baseline (speedup 1.0000x reference)
#include <cuda_runtime.h>
#include <cuda_bf16.h>
#include <cstdint>

// Problem constants
#define BB 4
#define LL 2048
#define DM 1024
#define DI 2048        // D_INNER
#define DS 16          // D_STATE
#define DC 4           // D_CONV
#define DTR 64         // DT_RANK
#define MM (BB*LL)     // 8192 rows
#define XDBL_W (DTR + 2*DS)   // 96

// ---------------- scratch (static device globals; no allocations) ----------------
__device__ float g_xr[(size_t)MM * (2*DI)];     // x_and_res  (8192 x 4096)
__device__ float g_xval[(size_t)MM * DI];       // post conv+silu
__device__ float g_xdbl[(size_t)MM * XDBL_W];   // dt_in | B | C
__device__ float g_dt[(size_t)MM * DI];         // softplus dt
__device__ float g_yg[(size_t)MM * DI];         // y * silu(res)

// ---------------- generic tiled SGEMM: C = A(MxK) * B(KxN), row-major ----------------
// epi: 0 = none, 1 = bias + softplus
__global__ void __launch_bounds__(256)
sgemm128(const float* __restrict__ A, const float* __restrict__ B, float* __restrict__ C,
         int M, int N, int K, int lda, int ldb, int ldc,
         const float* __restrict__ bias, int epi)
{
    __shared__ float As[8][128];
    __shared__ float Bs[8][128];

    const int tid  = threadIdx.x;
    const int row0 = blockIdx.y * 128;
    const int col0 = blockIdx.x * 128;

    // A tile load map: 2 threads per row, float4 each (8 cols = BK)
    const int aRow = tid >> 1;
    const int aCol = (tid & 1) << 2;
    // B tile load map: 32 threads per row (float4 each -> 128 cols), 8 rows
    const int bRow = tid >> 5;
    const int bCol = (tid & 31) << 2;

    const int ty = tid >> 4;    // 0..15
    const int tx = tid & 15;    // 0..15

    float acc[8][8];
    #pragma unroll
    for (int i = 0; i < 8; i++)
        #pragma unroll
        for (int j = 0; j < 8; j++) acc[i][j] = 0.0f;

    for (int k0 = 0; k0 < K; k0 += 8) {
        // load A tile (rows always in-range: M multiple of 128; K multiple of 8)
        float4 av = *(const float4*)(A + (size_t)(row0 + aRow) * lda + (k0 + aCol));
        As[aCol + 0][aRow] = av.x;
        As[aCol + 1][aRow] = av.y;
        As[aCol + 2][aRow] = av.z;
        As[aCol + 3][aRow] = av.w;

        // load B tile with N guard (cols multiple of 4; N multiple of 4)
        float4 bv = make_float4(0.f, 0.f, 0.f, 0.f);
        if (col0 + bCol < N)
            bv = *(const float4*)(B + (size_t)(k0 + bRow) * ldb + (col0 + bCol));
        Bs[bRow][bCol + 0] = bv.x;
        Bs[bRow][bCol + 1] = bv.y;
        Bs[bRow][bCol + 2] = bv.z;
        Bs[bRow][bCol + 3] = bv.w;

        __syncthreads();

        #pragma unroll
        for (int kk = 0; kk < 8; kk++) {
            float ar[8], br[8];
            float4 a0 = *(const float4*)&As[kk][ty * 8];
            float4 a1 = *(const float4*)&As[kk][ty * 8 + 4];
            float4 b0 = *(const float4*)&Bs[kk][tx * 8];
            float4 b1 = *(const float4*)&Bs[kk][tx * 8 + 4];
            ar[0]=a0.x; ar[1]=a0.y; ar[2]=a0.z; ar[3]=a0.w;
            ar[4]=a1.x; ar[5]=a1.y; ar[6]=a1.z; ar[7]=a1.w;
            br[0]=b0.x; br[1]=b0.y; br[2]=b0.z; br[3]=b0.w;
            br[4]=b1.x; br[5]=b1.y; br[6]=b1.z; br[7]=b1.w;
            #pragma unroll
            for (int i = 0; i < 8; i++)
                #pragma unroll
                for (int j = 0; j < 8; j++)
                    acc[i][j] = fmaf(ar[i], br[j], acc[i][j]);
        }
        __syncthreads();
    }

    // epilogue + store (guard columns)
    #pragma unroll
    for (int i = 0; i < 8; i++) {
        const int row = row0 + ty * 8 + i;
        #pragma unroll
        for (int j = 0; j < 8; j++) {
            const int col = col0 + tx * 8 + j;
            if (col < N) {
                float v = acc[i][j];
                if (epi == 1) {
                    v += bias[col];
                    // softplus
                    v = (v > 20.0f) ? v : log1pf(__expf(v));
                }
                C[(size_t)row * ldc + col] = v;
            }
        }
    }
}

// ---------------- causal depthwise conv (k=4) + SiLU ----------------
// reads x_val half of g_xr: element (b,l,d) at g_xr[(b*LL+l)*2*DI + d]
__global__ void conv_silu_kernel(const float* __restrict__ xr,
                                 const float* __restrict__ w,    // (DI, 4)
                                 const float* __restrict__ bias, // (DI,)
                                 float* __restrict__ out)        // (MM, DI)
{
    const int idx = blockIdx.x * blockDim.x + threadIdx.x;
    if (idx >= MM * DI) return;
    const int d = idx & (DI - 1);
    const int m = idx >> 11;
    const int l = m & (LL - 1);
    const int b = m >> 11;

    float acc = bias[d];
    #pragma unroll
    for (int i = 0; i < DC; i++) {
        const int lp = l + i - (DC - 1);
        if (lp >= 0)
            acc = fmaf(xr[((size_t)(b * LL + lp)) * (2 * DI) + d], w[d * DC + i], acc);
    }
    // silu
    out[idx] = acc * (1.0f / (1.0f + __expf(-acc)));
}

// ---------------- selective scan, one thread per (b, d) channel ----------------
// fuses y = C.h + D*u and the res-gate: yg = y * silu(res)
__global__ void __launch_bounds__(32)
scan_kernel(const float* __restrict__ dt,    // (MM, DI)
            const float* __restrict__ u,     // (MM, DI)
            const float* __restrict__ xdbl,  // (MM, 96)
            const float* __restrict__ logA,  // (DI, DS)
            const float* __restrict__ Dp,    // (DI,)
            const float* __restrict__ xr,    // (MM, 2*DI) -> res at +DI
            float* __restrict__ yg)          // (MM, DI)
{
    const int idx = blockIdx.x * blockDim.x + threadIdx.x;   // 0..8191
    const int d = idx & (DI - 1);
    const int b = idx >> 11;

    float A[DS], h[DS];
    #pragma unroll
    for (int n = 0; n < DS; n++) {
        A[n] = -__expf(logA[d * DS + n]);
        h[n] = 0.0f;
    }
    const float Dv = Dp[d];

    for (int l = 0; l < LL; l++) {
        const size_t m = (size_t)b * LL + l;
        const float dtv = dt[m * DI + d];
        const float uv  = u[m * DI + d];
        const float dtu = dtv * uv;

        const float4* bc = (const float4*)(xdbl + m * XDBL_W + DTR);
        float Bv[DS], Cv[DS];
        #pragma unroll
        for (int q = 0; q < 4; q++) {
            float4 t = bc[q];
            Bv[q*4+0]=t.x; Bv[q*4+1]=t.y; Bv[q*4+2]=t.z; Bv[q*4+3]=t.w;
        }
        #pragma unroll
        for (int q = 0; q < 4; q++) {
            float4 t = bc[4 + q];
            Cv[q*4+0]=t.x; Cv[q*4+1]=t.y; Cv[q*4+2]=t.z; Cv[q*4+3]=t.w;
        }

        float y = 0.0f;
        #pragma unroll
        for (int n = 0; n < DS; n++) {
            const float dA = __expf(dtv * A[n]);
            h[n] = fmaf(dA, h[n], dtu * Bv[n]);
            y = fmaf(Cv[n], h[n], y);
        }
        y = fmaf(Dv, uv, y);

        const float r = xr[m * (2 * DI) + DI + d];
        const float g = r * (1.0f / (1.0f + __expf(-r)));
        yg[m * DI + d] = y * g;
    }
}

// ---------------- host launcher ----------------
extern "C" void kernel_launch(void* const* d_in, const int* in_sizes, int n_in,
                              void* d_out, int out_size)
{
    const float* x      = (const float*)d_in[0];  // (B,L,DM)
    const float* W_in   = (const float*)d_in[1];  // (DM, 2*DI)
    const float* conv_w = (const float*)d_in[2];  // (DI, 4)
    const float* conv_b = (const float*)d_in[3];  // (DI,)
    const float* W_x    = (const float*)d_in[4];  // (DI, 96)
    const float* W_dt   = (const float*)d_in[5];  // (DTR, DI)
    const float* b_dt   = (const float*)d_in[6];  // (DI,)
    const float* logA   = (const float*)d_in[7];  // (DI, DS)
    const float* Dp     = (const float*)d_in[8];  // (DI,)
    const float* W_out  = (const float*)d_in[9];  // (DI, DM)
    float* out = (float*)d_out;

    float *xr, *xval, *xdbl, *dtb, *ygb;
    cudaGetSymbolAddress((void**)&xr,   g_xr);
    cudaGetSymbolAddress((void**)&xval, g_xval);
    cudaGetSymbolAddress((void**)&xdbl, g_xdbl);
    cudaGetSymbolAddress((void**)&dtb,  g_dt);
    cudaGetSymbolAddress((void**)&ygb,  g_yg);

    // 1) x @ W_in -> xr (8192 x 4096)
    {
        dim3 grid((2 * DI) / 128, MM / 128);
        sgemm128<<<grid, 256>>>(x, W_in, xr, MM, 2 * DI, DM, DM, 2 * DI, 2 * DI, nullptr, 0);
    }
    // 2) causal conv + silu -> xval (8192 x 2048)
    {
        int total = MM * DI;
        conv_silu_kernel<<<(total + 255) / 256, 256>>>(xr, conv_w, conv_b, xval);
    }
    // 3) xval @ W_x -> xdbl (8192 x 96)
    {
        dim3 grid((XDBL_W + 127) / 128, MM / 128);
        sgemm128<<<grid, 256>>>(xval, W_x, xdbl, MM, XDBL_W, DI, DI, XDBL_W, XDBL_W, nullptr, 0);
    }
    // 4) softplus(xdbl[:, :64] @ W_dt + b_dt) -> dt (8192 x 2048)
    {
        dim3 grid(DI / 128, MM / 128);
        sgemm128<<<grid, 256>>>(xdbl, W_dt, dtb, MM, DI, DTR, XDBL_W, DI, DI, b_dt, 1);
    }
    // 5) selective scan + gate -> yg (8192 x 2048)
    {
        scan_kernel<<<(BB * DI) / 32, 32>>>(dtb, xval, xdbl, logA, Dp, xr, ygb);
    }
    // 6) yg @ W_out -> out (8192 x 1024)
    {
        dim3 grid(DM / 128, MM / 128);
        sgemm128<<<grid, 256>>>(ygb, W_out, out, MM, DM, DI, DI, DM, DM, nullptr, 0);
    }
}

// round 3
// speedup vs baseline: 3.1992x; 3.1992x over previous
#include <cuda_runtime.h>
#include <cuda_bf16.h>
#include <cstdint>

// Problem constants
#define BB 4
#define LL 2048
#define DM 1024
#define DI 2048        // D_INNER
#define DS 16          // D_STATE
#define DC 4           // D_CONV
#define DTR 64         // DT_RANK
#define MM (BB*LL)     // 8192 rows
#define XDBL_W (DTR + 2*DS)   // 96
#define NCH 8          // scan chunks
#define CL (LL/NCH)    // 256 steps per chunk

// ---------------- scratch (static device globals; no allocations) ----------------
__device__ __align__(16) float g_xr[(size_t)MM * (2*DI)];     // x_and_res
__device__ __align__(16) float g_xval[(size_t)MM * DI];       // post conv+silu (fp32 for scan)
__device__ __align__(16) float g_xdbl[(size_t)MM * XDBL_W];   // dt_in | B | C
__device__ __align__(16) float g_dt[(size_t)MM * DI];         // softplus dt
__device__ __align__(16) float g_H[(size_t)BB * NCH * DS * DI];  // chunk-local final h
__device__ __align__(16) float g_P[(size_t)BB * NCH * DS * DI];  // chunk prod(dA)

// split activations (bf16 hi/lo), row-major M x K
__device__ __align__(16) __nv_bfloat16 g_xh [(size_t)MM * DM];
__device__ __align__(16) __nv_bfloat16 g_xl [(size_t)MM * DM];
__device__ __align__(16) __nv_bfloat16 g_xvh[(size_t)MM * DI];
__device__ __align__(16) __nv_bfloat16 g_xvl[(size_t)MM * DI];
__device__ __align__(16) __nv_bfloat16 g_dth[(size_t)MM * DTR];
__device__ __align__(16) __nv_bfloat16 g_dtl[(size_t)MM * DTR];
__device__ __align__(16) __nv_bfloat16 g_ygh[(size_t)MM * DI];
__device__ __align__(16) __nv_bfloat16 g_ygl[(size_t)MM * DI];

// transposed + split weights (bf16 hi/lo), layout (N, K) row-major
__device__ __align__(16) __nv_bfloat16 g_winT_h[(size_t)(2*DI) * DM];
__device__ __align__(16) __nv_bfloat16 g_winT_l[(size_t)(2*DI) * DM];
__device__ __align__(16) __nv_bfloat16 g_wxT_h[(size_t)128 * DI];   // rows 96..127 stay zero
__device__ __align__(16) __nv_bfloat16 g_wxT_l[(size_t)128 * DI];
__device__ __align__(16) __nv_bfloat16 g_wdtT_h[(size_t)DI * DTR];
__device__ __align__(16) __nv_bfloat16 g_wdtT_l[(size_t)DI * DTR];
__device__ __align__(16) __nv_bfloat16 g_woutT_h[(size_t)DM * DI];
__device__ __align__(16) __nv_bfloat16 g_woutT_l[(size_t)DM * DI];

// ===================== low-level helpers =====================
__device__ __forceinline__ uint32_t smem_u32(const void* p) {
    uint32_t a;
    asm("{ .reg .u64 t; cvta.to.shared.u64 t, %1; cvt.u32.u64 %0, t; }" : "=r"(a) : "l"(p));
    return a;
}
__device__ __forceinline__ void cpa16(uint32_t s, const void* g) {
    asm volatile("cp.async.cg.shared.global [%0], [%1], 16;" :: "r"(s), "l"(g));
}
#define CP_COMMIT() asm volatile("cp.async.commit_group;")
#define CP_WAIT(n)  asm volatile("cp.async.wait_group %0;" :: "n"(n))

__device__ __forceinline__ void ldsm4(uint32_t* r, uint32_t addr) {
    asm volatile("ldmatrix.sync.aligned.m8n8.x4.shared.b16 {%0,%1,%2,%3}, [%4];"
        : "=r"(r[0]), "=r"(r[1]), "=r"(r[2]), "=r"(r[3]) : "r"(addr));
}
__device__ __forceinline__ void mma16816(float* d, const uint32_t* a, const uint32_t* b) {
    asm volatile(
        "mma.sync.aligned.m16n8k16.row.col.f32.bf16.bf16.f32 "
        "{%0,%1,%2,%3}, {%4,%5,%6,%7}, {%8,%9}, {%0,%1,%2,%3};"
        : "+f"(d[0]), "+f"(d[1]), "+f"(d[2]), "+f"(d[3])
        : "r"(a[0]), "r"(a[1]), "r"(a[2]), "r"(a[3]), "r"(b[0]), "r"(b[1]));
}
__device__ __forceinline__ void bf16split(float v, __nv_bfloat16& h, __nv_bfloat16& l) {
    h = __float2bfloat16(v);
    l = __float2bfloat16(v - __bfloat162float(h));
}

// ================= HMMA GEMM: C(M,N) = A(M,K) @ B(N,K)^T, split-bf16 3-term =================
// tiles: 128x128x64; smem per stage = 4 x 16KB (Ah, Al, Bh, Bl); 2 stages = 128KB
#define TILE_B 16384
#define HG_SMEM (2 * 4 * TILE_B)

__global__ void __launch_bounds__(256, 1)
hgemm(const __nv_bfloat16* __restrict__ Ah, const __nv_bfloat16* __restrict__ Al,
      const __nv_bfloat16* __restrict__ Bh, const __nv_bfloat16* __restrict__ Bl,
      float* __restrict__ C, int N, int K, int ldc,
      const float* __restrict__ bias, int epi)
{
    extern __shared__ char smem[];
    const uint32_t sb = smem_u32(smem);
    const int tid  = threadIdx.x;
    const int wid  = tid >> 5;
    const int lane = tid & 31;
    const int row0 = blockIdx.y * 128;
    const int col0 = blockIdx.x * 128;
    const int wm = wid >> 1;   // 0..3 (M)
    const int wn = wid & 1;    // 0..1 (N)

    float acc[2][8][4];
    #pragma unroll
    for (int i = 0; i < 2; i++)
        #pragma unroll
        for (int j = 0; j < 8; j++)
            #pragma unroll
            for (int q = 0; q < 4; q++) acc[i][j][q] = 0.0f;

    const int KT = K >> 6;

    // ---- stage loader: 1024 x 16B chunks per operand, SW128 swizzle ----
    auto load_stage = [&](int s, int k0) {
        const uint32_t base = sb + (uint32_t)s * 4 * TILE_B;
        #pragma unroll
        for (int i = 0; i < 4; i++) {
            const int lin = tid + i * 256;           // 0..1023
            const int r = lin >> 3, c = lin & 7;
            const uint32_t so = (uint32_t)(r * 128 + ((c ^ (r & 7)) << 4));
            const size_t ga = (size_t)(row0 + r) * K + k0 + c * 8;
            const size_t gb = (size_t)(col0 + r) * K + k0 + c * 8;
            cpa16(base +              so, Ah + ga);
            cpa16(base +     TILE_B + so, Al + ga);
            cpa16(base + 2 * TILE_B + so, Bh + gb);
            cpa16(base + 3 * TILE_B + so, Bl + gb);
        }
        CP_COMMIT();
    };

    // ---- compute one 64-deep K stage ----
    auto compute_stage = [&](int s) {
        const uint32_t base = sb + (uint32_t)s * 4 * TILE_B;
        #pragma unroll
        for (int ks = 0; ks < 4; ks++) {
            uint32_t ah[2][4], al[2][4];
            #pragma unroll
            for (int mt = 0; mt < 2; mt++) {
                const int R = wm * 32 + mt * 16 + (lane & 15);
                const int c = ks * 2 + (lane >> 4);
                const uint32_t ad = base + (uint32_t)(R * 128 + ((c ^ (R & 7)) << 4));
                ldsm4(ah[mt], ad);
                ldsm4(al[mt], ad + TILE_B);
            }
            uint32_t bh[4][4], bl[4][4];
            #pragma unroll
            for (int g = 0; g < 4; g++) {
                const int R = wn * 64 + g * 16 + (lane & 7) + ((lane >> 4) & 1) * 8;
                const int c = ks * 2 + ((lane >> 3) & 1);
                const uint32_t bd = base + 2 * TILE_B + (uint32_t)(R * 128 + ((c ^ (R & 7)) << 4));
                ldsm4(bh[g], bd);
                ldsm4(bl[g], bd + TILE_B);
            }
            #pragma unroll
            for (int mt = 0; mt < 2; mt++)
                #pragma unroll
                for (int g = 0; g < 4; g++)
                    #pragma unroll
                    for (int sub = 0; sub < 2; sub++) {
                        float* d = acc[mt][g * 2 + sub];
                        mma16816(d, ah[mt], &bh[g][sub * 2]);
                        mma16816(d, ah[mt], &bl[g][sub * 2]);
                        mma16816(d, al[mt], &bh[g][sub * 2]);
                    }
        }
    };

    load_stage(0, 0);
    for (int kt = 0; kt < KT; kt++) {
        if (kt + 1 < KT) {
            load_stage((kt + 1) & 1, (kt + 1) * 64);
            CP_WAIT(1);
        } else {
            CP_WAIT(0);
        }
        __syncthreads();
        compute_stage(kt & 1);
        __syncthreads();
    }

    // ---- epilogue ----
    #pragma unroll
    for (int mt = 0; mt < 2; mt++) {
        const int row = row0 + wm * 32 + mt * 16 + (lane >> 2);
        #pragma unroll
        for (int j = 0; j < 8; j++) {
            const int col = col0 + wn * 64 + j * 8 + (lane & 3) * 2;
            if (col < N) {
                float v0 = acc[mt][j][0], v1 = acc[mt][j][1];
                float v2 = acc[mt][j][2], v3 = acc[mt][j][3];
                if (epi == 1) {
                    const float b0 = bias[col], b1 = bias[col + 1];
                    v0 += b0; v0 = (v0 > 20.0f) ? v0 : log1pf(__expf(v0));
                    v1 += b1; v1 = (v1 > 20.0f) ? v1 : log1pf(__expf(v1));
                    v2 += b0; v2 = (v2 > 20.0f) ? v2 : log1pf(__expf(v2));
                    v3 += b1; v3 = (v3 > 20.0f) ? v3 : log1pf(__expf(v3));
                }
                *(float2*)(C + (size_t)row * ldc + col)       = make_float2(v0, v1);
                *(float2*)(C + (size_t)(row + 8) * ldc + col) = make_float2(v2, v3);
            }
        }
    }
}

// ---------------- weight transpose + bf16 split: W(K,N) -> Th/Tl (N,K) ----------------
__global__ void __launch_bounds__(256)
tsplit(const float* __restrict__ W, __nv_bfloat16* __restrict__ Th, __nv_bfloat16* __restrict__ Tl,
       int K, int N)
{
    __shared__ float t[32][33];
    const int n0 = blockIdx.x * 32;
    const int k0 = blockIdx.y * 32;
    const int tx = threadIdx.x & 31;
    const int ty = threadIdx.x >> 5;
    #pragma unroll
    for (int i = 0; i < 32; i += 8)
        t[ty + i][tx] = W[(size_t)(k0 + ty + i) * N + (n0 + tx)];
    __syncthreads();
    #pragma unroll
    for (int i = 0; i < 32; i += 8) {
        __nv_bfloat16 h, l;
        bf16split(t[tx][ty + i], h, l);
        Th[(size_t)(n0 + ty + i) * K + (k0 + tx)] = h;
        Tl[(size_t)(n0 + ty + i) * K + (k0 + tx)] = l;
    }
}

// ---------------- fp32 -> bf16 hi/lo split (dense) ----------------
__global__ void __launch_bounds__(256)
split_plain(const float* __restrict__ in, __nv_bfloat16* __restrict__ h,
            __nv_bfloat16* __restrict__ l, int n4)
{
    const int i = blockIdx.x * blockDim.x + threadIdx.x;
    if (i >= n4) return;
    const float4 v = ((const float4*)in)[i];
    __nv_bfloat16 hh[4], ll[4];
    bf16split(v.x, hh[0], ll[0]);
    bf16split(v.y, hh[1], ll[1]);
    bf16split(v.z, hh[2], ll[2]);
    bf16split(v.w, hh[3], ll[3]);
    ((uint2*)h)[i] = make_uint2(
        (uint32_t)__bfloat16_as_ushort(hh[0]) | ((uint32_t)__bfloat16_as_ushort(hh[1]) << 16),
        (uint32_t)__bfloat16_as_ushort(hh[2]) | ((uint32_t)__bfloat16_as_ushort(hh[3]) << 16));
    ((uint2*)l)[i] = make_uint2(
        (uint32_t)__bfloat16_as_ushort(ll[0]) | ((uint32_t)__bfloat16_as_ushort(ll[1]) << 16),
        (uint32_t)__bfloat16_as_ushort(ll[2]) | ((uint32_t)__bfloat16_as_ushort(ll[3]) << 16));
}

// ---------------- xdbl cols 0..63 -> dt hi/lo (8192 x 64) ----------------
__global__ void __launch_bounds__(256)
split_dt(const float* __restrict__ xdbl, __nv_bfloat16* __restrict__ h, __nv_bfloat16* __restrict__ l)
{
    const int i = blockIdx.x * blockDim.x + threadIdx.x;
    if (i >= MM * DTR) return;
    const int r = i >> 6, c = i & 63;
    __nv_bfloat16 hh, ll;
    bf16split(xdbl[(size_t)r * XDBL_W + c], hh, ll);
    h[i] = hh; l[i] = ll;
}

// ---------------- causal depthwise conv (k=4) + SiLU, fused bf16 split ----------------
__global__ void __launch_bounds__(256)
conv_silu_kernel(const float* __restrict__ xr, const float* __restrict__ w,
                 const float* __restrict__ bias, float* __restrict__ out,
                 __nv_bfloat16* __restrict__ oh, __nv_bfloat16* __restrict__ ol)
{
    const int idx = blockIdx.x * blockDim.x + threadIdx.x;
    if (idx >= MM * DI) return;
    const int d = idx & (DI - 1);
    const int m = idx >> 11;
    const int l = m & (LL - 1);
    const int b = m >> 11;

    float acc = bias[d];
    #pragma unroll
    for (int i = 0; i < DC; i++) {
        const int lp = l + i - (DC - 1);
        if (lp >= 0)
            acc = fmaf(xr[((size_t)(b * LL + lp)) * (2 * DI) + d], w[d * DC + i], acc);
    }
    const float v = acc * (1.0f / (1.0f + __expf(-acc)));
    out[idx] = v;
    __nv_bfloat16 hh, ll;
    bf16split(v, hh, ll);
    oh[idx] = hh; ol[idx] = ll;
}

// ---------------- chunked selective scan: pass 1 (chunk-local h and prod dA) ----------------
__global__ void __launch_bounds__(256)
scan_p1(const float* __restrict__ dt, const float* __restrict__ u,
        const float* __restrict__ xdbl, const float* __restrict__ logA,
        float* __restrict__ H, float* __restrict__ P)
{
    const int idx = blockIdx.x * 256 + threadIdx.x;      // 65536
    const int d = idx & (DI - 1);
    const int t = idx >> 11;
    const int c = t & (NCH - 1);
    const int b = t >> 3;

    float A[DS];
    #pragma unroll
    for (int n = 0; n < DS; n++) A[n] = -__expf(logA[d * DS + n]);
    const float A0 = A[0];
    bool pw = true;
    #pragma unroll
    for (int n = 1; n < DS; n++)
        pw = pw && (fabsf(A[n] - (float)(n + 1) * A0) <= 1e-5f * fabsf(A[n]));

    float h[DS], Pr[DS];
    #pragma unroll
    for (int n = 0; n < DS; n++) { h[n] = 0.0f; Pr[n] = 1.0f; }

    const int l0 = c * CL;
    for (int l = l0; l < l0 + CL; l++) {
        const size_t m = (size_t)b * LL + l;
        const float dtv = dt[m * DI + d];
        const float uv  = u[m * DI + d];
        const float dtu = dtv * uv;

        float e[DS];
        if (pw) {
            const float e1 = __expf(dtv * A0);
            float p = e1;
            e[0] = p;
            #pragma unroll
            for (int n = 1; n < DS; n++) { p *= e1; e[n] = p; }
        } else {
            #pragma unroll
            for (int n = 0; n < DS; n++) e[n] = __expf(dtv * A[n]);
        }

        const float4* bp = (const float4*)(xdbl + m * XDBL_W + DTR);
        float Bv[DS];
        #pragma unroll
        for (int q = 0; q < 4; q++) {
            const float4 v = bp[q];
            Bv[q*4+0]=v.x; Bv[q*4+1]=v.y; Bv[q*4+2]=v.z; Bv[q*4+3]=v.w;
        }
        #pragma unroll
        for (int n = 0; n < DS; n++) {
            h[n] = fmaf(e[n], h[n], dtu * Bv[n]);
            Pr[n] *= e[n];
        }
    }
    const size_t o = ((size_t)(b * NCH + c) * DS) * DI + d;
    #pragma unroll
    for (int n = 0; n < DS; n++) { H[o + (size_t)n * DI] = h[n]; P[o + (size_t)n * DI] = Pr[n]; }
}

// ---------------- chunked scan: pass 2 (recombine + y + gate + bf16 split) ----------------
__global__ void __launch_bounds__(256)
scan_p2(const float* __restrict__ dt, const float* __restrict__ u,
        const float* __restrict__ xdbl, const float* __restrict__ logA,
        const float* __restrict__ Dp, const float* __restrict__ xr,
        const float* __restrict__ H, const float* __restrict__ P,
        __nv_bfloat16* __restrict__ ygh, __nv_bfloat16* __restrict__ ygl)
{
    const int idx = blockIdx.x * 256 + threadIdx.x;
    const int d = idx & (DI - 1);
    const int t = idx >> 11;
    const int c = t & (NCH - 1);
    const int b = t >> 3;

    float A[DS];
    #pragma unroll
    for (int n = 0; n < DS; n++) A[n] = -__expf(logA[d * DS + n]);
    const float A0 = A[0];
    bool pw = true;
    #pragma unroll
    for (int n = 1; n < DS; n++)
        pw = pw && (fabsf(A[n] - (float)(n + 1) * A0) <= 1e-5f * fabsf(A[n]));

    // recombine preceding chunk states
    float h[DS];
    #pragma unroll
    for (int n = 0; n < DS; n++) h[n] = 0.0f;
    for (int j = 0; j < c; j++) {
        const size_t o = ((size_t)(b * NCH + j) * DS) * DI + d;
        #pragma unroll
        for (int n = 0; n < DS; n++)
            h[n] = fmaf(P[o + (size_t)n * DI], h[n], H[o + (size_t)n * DI]);
    }
    const float Dv = Dp[d];

    const int l0 = c * CL;
    for (int l = l0; l < l0 + CL; l++) {
        const size_t m = (size_t)b * LL + l;
        const float dtv = dt[m * DI + d];
        const float uv  = u[m * DI + d];
        const float dtu = dtv * uv;

        float e[DS];
        if (pw) {
            const float e1 = __expf(dtv * A0);
            float p = e1;
            e[0] = p;
            #pragma unroll
            for (int n = 1; n < DS; n++) { p *= e1; e[n] = p; }
        } else {
            #pragma unroll
            for (int n = 0; n < DS; n++) e[n] = __expf(dtv * A[n]);
        }

        const float4* bp = (const float4*)(xdbl + m * XDBL_W + DTR);
        float Bv[DS], Cv[DS];
        #pragma unroll
        for (int q = 0; q < 4; q++) {
            const float4 v = bp[q];
            Bv[q*4+0]=v.x; Bv[q*4+1]=v.y; Bv[q*4+2]=v.z; Bv[q*4+3]=v.w;
        }
        #pragma unroll
        for (int q = 0; q < 4; q++) {
            const float4 v = bp[4 + q];
            Cv[q*4+0]=v.x; Cv[q*4+1]=v.y; Cv[q*4+2]=v.z; Cv[q*4+3]=v.w;
        }

        float y = 0.0f;
        #pragma unroll
        for (int n = 0; n < DS; n++) {
            h[n] = fmaf(e[n], h[n], dtu * Bv[n]);
            y = fmaf(Cv[n], h[n], y);
        }
        y = fmaf(Dv, uv, y);

        const float r = xr[m * (2 * DI) + DI + d];
        const float g = r * (1.0f / (1.0f + __expf(-r)));
        const float yg = y * g;
        __nv_bfloat16 hh, ll;
        bf16split(yg, hh, ll);
        ygh[m * DI + d] = hh;
        ygl[m * DI + d] = ll;
    }
}

// ---------------- host launcher ----------------
extern "C" void kernel_launch(void* const* d_in, const int* in_sizes, int n_in,
                              void* d_out, int out_size)
{
    const float* x      = (const float*)d_in[0];
    const float* W_in   = (const float*)d_in[1];
    const float* conv_w = (const float*)d_in[2];
    const float* conv_b = (const float*)d_in[3];
    const float* W_x    = (const float*)d_in[4];
    const float* W_dt   = (const float*)d_in[5];
    const float* b_dt   = (const float*)d_in[6];
    const float* logA   = (const float*)d_in[7];
    const float* Dp     = (const float*)d_in[8];
    const float* W_out  = (const float*)d_in[9];
    float* out = (float*)d_out;

    cudaFuncSetAttribute(hgemm, cudaFuncAttributeMaxDynamicSharedMemorySize, HG_SMEM);

    float *xr, *xval, *xdbl, *dtb, *Hb, *Pb;
    cudaGetSymbolAddress((void**)&xr,   g_xr);
    cudaGetSymbolAddress((void**)&xval, g_xval);
    cudaGetSymbolAddress((void**)&xdbl, g_xdbl);
    cudaGetSymbolAddress((void**)&dtb,  g_dt);
    cudaGetSymbolAddress((void**)&Hb,   g_H);
    cudaGetSymbolAddress((void**)&Pb,   g_P);

    __nv_bfloat16 *xh, *xl, *xvh, *xvl, *dth, *dtl, *ygh, *ygl;
    cudaGetSymbolAddress((void**)&xh,  g_xh);
    cudaGetSymbolAddress((void**)&xl,  g_xl);
    cudaGetSymbolAddress((void**)&xvh, g_xvh);
    cudaGetSymbolAddress((void**)&xvl, g_xvl);
    cudaGetSymbolAddress((void**)&dth, g_dth);
    cudaGetSymbolAddress((void**)&dtl, g_dtl);
    cudaGetSymbolAddress((void**)&ygh, g_ygh);
    cudaGetSymbolAddress((void**)&ygl, g_ygl);

    __nv_bfloat16 *winh, *winl, *wxh, *wxl, *wdth, *wdtl, *wouth, *woutl;
    cudaGetSymbolAddress((void**)&winh,  g_winT_h);
    cudaGetSymbolAddress((void**)&winl,  g_winT_l);
    cudaGetSymbolAddress((void**)&wxh,   g_wxT_h);
    cudaGetSymbolAddress((void**)&wxl,   g_wxT_l);
    cudaGetSymbolAddress((void**)&wdth,  g_wdtT_h);
    cudaGetSymbolAddress((void**)&wdtl,  g_wdtT_l);
    cudaGetSymbolAddress((void**)&wouth, g_woutT_h);
    cudaGetSymbolAddress((void**)&woutl, g_woutT_l);

    // weight prep: transpose + split
    tsplit<<<dim3((2*DI)/32, DM/32), 256>>>(W_in, winh, winl, DM, 2*DI);
    tsplit<<<dim3(XDBL_W/32, DI/32), 256>>>(W_x, wxh, wxl, DI, XDBL_W);
    tsplit<<<dim3(DI/32, DTR/32), 256>>>(W_dt, wdth, wdtl, DTR, DI);
    tsplit<<<dim3(DM/32, DI/32), 256>>>(W_out, wouth, woutl, DI, DM);

    // split x
    split_plain<<<(MM*DM/4 + 255)/256, 256>>>(x, xh, xl, MM*DM/4);

    // 1) x @ W_in -> xr (8192 x 4096)
    hgemm<<<dim3((2*DI)/128, MM/128), 256, HG_SMEM>>>(
        xh, xl, winh, winl, xr, 2*DI, DM, 2*DI, nullptr, 0);

    // 2) causal conv + silu -> xval fp32 + hi/lo
    conv_silu_kernel<<<(MM*DI + 255)/256, 256>>>(xr, conv_w, conv_b, xval, xvh, xvl);

    // 3) xval @ W_x -> xdbl (8192 x 96), N padded to 128 by zero B rows
    hgemm<<<dim3(1, MM/128), 256, HG_SMEM>>>(
        xvh, xvl, wxh, wxl, xdbl, XDBL_W, DI, XDBL_W, nullptr, 0);

    // split dt input cols
    split_dt<<<(MM*DTR + 255)/256, 256>>>(xdbl, dth, dtl);

    // 4) softplus(dt_in @ W_dt + b_dt) -> dt (8192 x 2048), K=64
    hgemm<<<dim3(DI/128, MM/128), 256, HG_SMEM>>>(
        dth, dtl, wdth, wdtl, dtb, DI, DTR, DI, b_dt, 1);

    // 5) chunked selective scan
    scan_p1<<<(BB*DI*NCH)/256, 256>>>(dtb, xval, xdbl, logA, Hb, Pb);
    scan_p2<<<(BB*DI*NCH)/256, 256>>>(dtb, xval, xdbl, logA, Dp, xr, Hb, Pb, ygh, ygl);

    // 6) yg @ W_out -> out (8192 x 1024)
    hgemm<<<dim3(DM/128, MM/128), 256, HG_SMEM>>>(
        ygh, ygl, wouth, woutl, out, DM, DI, DM, nullptr, 0);
}

// round 4
// speedup vs baseline: 3.2953x; 1.0300x over previous
#include <cuda_runtime.h>
#include <cuda_bf16.h>
#include <cstdint>

// Problem constants
#define BB 4
#define LL 2048
#define DM 1024
#define DI 2048        // D_INNER
#define DS 16          // D_STATE
#define DC 4           // D_CONV
#define DTR 64         // DT_RANK
#define MM (BB*LL)     // 8192 rows
#define XDBL_W (DTR + 2*DS)   // 96
#define NCH 8          // scan chunks
#define CL (LL/NCH)    // 256 steps per chunk

// ---------------- scratch (static device globals; no allocations) ----------------
__device__ __align__(16) float g_xr[(size_t)MM * (2*DI)];     // x_and_res
__device__ __align__(16) float g_xval[(size_t)MM * DI];       // post conv+silu (fp32 for scan)
__device__ __align__(16) float g_xdbl[(size_t)MM * XDBL_W];   // dt_in | B | C
__device__ __align__(16) float g_dt[(size_t)MM * DI];         // softplus dt
__device__ __align__(16) float g_H[(size_t)BB * NCH * DS * DI];  // chunk-local final h
__device__ __align__(16) float g_P[(size_t)BB * NCH * DS * DI];  // chunk prod(dA)
__device__ __align__(16) float g_part[(size_t)4 * MM * 128];     // split-K partials (GEMM2)

// split activations (bf16 hi/lo), row-major M x K
__device__ __align__(16) __nv_bfloat16 g_xh [(size_t)MM * DM];
__device__ __align__(16) __nv_bfloat16 g_xl [(size_t)MM * DM];
__device__ __align__(16) __nv_bfloat16 g_xvh[(size_t)MM * DI];
__device__ __align__(16) __nv_bfloat16 g_xvl[(size_t)MM * DI];
__device__ __align__(16) __nv_bfloat16 g_dth[(size_t)MM * DTR];
__device__ __align__(16) __nv_bfloat16 g_dtl[(size_t)MM * DTR];
__device__ __align__(16) __nv_bfloat16 g_ygh[(size_t)MM * DI];
__device__ __align__(16) __nv_bfloat16 g_ygl[(size_t)MM * DI];

// transposed + split weights (bf16 hi/lo), layout (N, K) row-major
__device__ __align__(16) __nv_bfloat16 g_winT_h[(size_t)(2*DI) * DM];
__device__ __align__(16) __nv_bfloat16 g_winT_l[(size_t)(2*DI) * DM];
__device__ __align__(16) __nv_bfloat16 g_wxT_h[(size_t)128 * DI];   // rows 96..127 stay zero
__device__ __align__(16) __nv_bfloat16 g_wxT_l[(size_t)128 * DI];
__device__ __align__(16) __nv_bfloat16 g_wdtT_h[(size_t)DI * DTR];
__device__ __align__(16) __nv_bfloat16 g_wdtT_l[(size_t)DI * DTR];
__device__ __align__(16) __nv_bfloat16 g_woutT_h[(size_t)DM * DI];
__device__ __align__(16) __nv_bfloat16 g_woutT_l[(size_t)DM * DI];

// ===================== low-level helpers =====================
__device__ __forceinline__ uint32_t smem_u32(const void* p) {
    uint32_t a;
    asm("{ .reg .u64 t; cvta.to.shared.u64 t, %1; cvt.u32.u64 %0, t; }" : "=r"(a) : "l"(p));
    return a;
}
__device__ __forceinline__ void cpa16(uint32_t s, const void* g) {
    asm volatile("cp.async.cg.shared.global [%0], [%1], 16;" :: "r"(s), "l"(g));
}
#define CP_COMMIT() asm volatile("cp.async.commit_group;")
#define CP_WAIT(n)  asm volatile("cp.async.wait_group %0;" :: "n"(n))

__device__ __forceinline__ void ldsm4(uint32_t* r, uint32_t addr) {
    asm volatile("ldmatrix.sync.aligned.m8n8.x4.shared.b16 {%0,%1,%2,%3}, [%4];"
        : "=r"(r[0]), "=r"(r[1]), "=r"(r[2]), "=r"(r[3]) : "r"(addr));
}
__device__ __forceinline__ void mma16816(float* d, const uint32_t* a, const uint32_t* b) {
    asm volatile(
        "mma.sync.aligned.m16n8k16.row.col.f32.bf16.bf16.f32 "
        "{%0,%1,%2,%3}, {%4,%5,%6,%7}, {%8,%9}, {%0,%1,%2,%3};"
        : "+f"(d[0]), "+f"(d[1]), "+f"(d[2]), "+f"(d[3])
        : "r"(a[0]), "r"(a[1]), "r"(a[2]), "r"(a[3]), "r"(b[0]), "r"(b[1]));
}
__device__ __forceinline__ void bf16split(float v, __nv_bfloat16& h, __nv_bfloat16& l) {
    h = __float2bfloat16(v);
    l = __float2bfloat16(v - __bfloat162float(h));
}

// ================= HMMA GEMM: C(M,N=128/CTA) = A(M,K) @ B(N,K)^T, split-bf16 3-term =================
// CTAM x 128 CTA tile, BK=64, 8 warps; warp tile 64 x WN.
// CTAM=256 -> WN=64 (warps 4Mx2N); CTAM=128 -> WN=32 (warps 2Mx4N).
template<int CTAM, int WN>
__global__ void __launch_bounds__(256, 1)
hgemm(const __nv_bfloat16* __restrict__ Ah, const __nv_bfloat16* __restrict__ Al,
      const __nv_bfloat16* __restrict__ Bh, const __nv_bfloat16* __restrict__ Bl,
      float* __restrict__ C, int N, int K, int ldc,
      const float* __restrict__ bias, int epi, int kslice, size_t zstride)
{
    constexpr int MW  = CTAM / 64;      // warps along M
    constexpr int G   = WN / 16;        // n16 groups per warp
    constexpr int NJ  = WN / 8;         // n8 frags per warp
    constexpr int ASZ = CTAM * 128;     // bytes of one A term per stage
    constexpr int BSZ = 16384;          // bytes of one B term per stage
    constexpr int STAGE = 2 * ASZ + 2 * BSZ;

    extern __shared__ char smem[];
    const uint32_t sb = smem_u32(smem);
    const int tid  = threadIdx.x;
    const int wid  = tid >> 5;
    const int lane = tid & 31;
    const int row0 = blockIdx.y * CTAM;
    const int col0 = blockIdx.x * 128;
    const int wm = wid & (MW - 1);
    const int wn = wid / MW;

    const int kbase = blockIdx.z * kslice;
    C += (size_t)blockIdx.z * zstride;
    const int KT = kslice >> 6;

    float acc[4][NJ][4];
    #pragma unroll
    for (int i = 0; i < 4; i++)
        #pragma unroll
        for (int j = 0; j < NJ; j++)
            #pragma unroll
            for (int q = 0; q < 4; q++) acc[i][j][q] = 0.0f;

    auto load_stage = [&](int s, int k0) {
        const uint32_t base = sb + (uint32_t)s * STAGE;
        #pragma unroll
        for (int i = 0; i < CTAM / 32; i++) {
            const int lin = tid + i * 256;
            const int r = lin >> 3, c = lin & 7;
            const uint32_t so = (uint32_t)(r * 128 + ((c ^ (r & 7)) << 4));
            const size_t ga = (size_t)(row0 + r) * K + k0 + c * 8;
            cpa16(base +       so, Ah + ga);
            cpa16(base + ASZ + so, Al + ga);
        }
        #pragma unroll
        for (int i = 0; i < 4; i++) {
            const int lin = tid + i * 256;
            const int r = lin >> 3, c = lin & 7;
            const uint32_t so = (uint32_t)(r * 128 + ((c ^ (r & 7)) << 4));
            const size_t gb = (size_t)(col0 + r) * K + k0 + c * 8;
            cpa16(base + 2 * ASZ +       so, Bh + gb);
            cpa16(base + 2 * ASZ + BSZ + so, Bl + gb);
        }
        CP_COMMIT();
    };

    auto compute_stage = [&](int s) {
        const uint32_t aBase = sb + (uint32_t)s * STAGE;
        const uint32_t bBase = aBase + 2 * ASZ;
        #pragma unroll
        for (int ks = 0; ks < 4; ks++) {
            uint32_t ah[4][4], al[4][4];
            #pragma unroll
            for (int mt = 0; mt < 4; mt++) {
                const int R = wm * 64 + mt * 16 + (lane & 15);
                const int c = ks * 2 + (lane >> 4);
                const uint32_t ad = aBase + (uint32_t)(R * 128 + ((c ^ (R & 7)) << 4));
                ldsm4(ah[mt], ad);
                ldsm4(al[mt], ad + ASZ);
            }
            #pragma unroll
            for (int g = 0; g < G; g++) {
                const int R = wn * WN + g * 16 + (lane & 7) + ((lane >> 4) & 1) * 8;
                const int c = ks * 2 + ((lane >> 3) & 1);
                const uint32_t bd = bBase + (uint32_t)(R * 128 + ((c ^ (R & 7)) << 4));
                uint32_t bh[4], bl[4];
                ldsm4(bh, bd);
                ldsm4(bl, bd + BSZ);
                #pragma unroll
                for (int mt = 0; mt < 4; mt++)
                    #pragma unroll
                    for (int sub = 0; sub < 2; sub++) {
                        float* d = acc[mt][g * 2 + sub];
                        mma16816(d, ah[mt], &bh[sub * 2]);
                        mma16816(d, ah[mt], &bl[sub * 2]);
                        mma16816(d, al[mt], &bh[sub * 2]);
                    }
            }
        }
    };

    load_stage(0, kbase);
    for (int kt = 0; kt < KT; kt++) {
        if (kt + 1 < KT) {
            load_stage((kt + 1) & 1, kbase + (kt + 1) * 64);
            CP_WAIT(1);
        } else {
            CP_WAIT(0);
        }
        __syncthreads();
        compute_stage(kt & 1);
        __syncthreads();
    }

    // ---- epilogue (N per CTA always full 128; all problem N are multiples of 128) ----
    #pragma unroll
    for (int mt = 0; mt < 4; mt++) {
        const int row = row0 + wm * 64 + mt * 16 + (lane >> 2);
        #pragma unroll
        for (int j = 0; j < NJ; j++) {
            const int col = col0 + wn * WN + j * 8 + (lane & 3) * 2;
            float v0 = acc[mt][j][0], v1 = acc[mt][j][1];
            float v2 = acc[mt][j][2], v3 = acc[mt][j][3];
            if (epi == 1) {
                const float b0 = bias[col], b1 = bias[col + 1];
                v0 += b0; v0 = (v0 > 20.0f) ? v0 : log1pf(__expf(v0));
                v1 += b1; v1 = (v1 > 20.0f) ? v1 : log1pf(__expf(v1));
                v2 += b0; v2 = (v2 > 20.0f) ? v2 : log1pf(__expf(v2));
                v3 += b1; v3 = (v3 > 20.0f) ? v3 : log1pf(__expf(v3));
            }
            *(float2*)(C + (size_t)row * ldc + col)       = make_float2(v0, v1);
            *(float2*)(C + (size_t)(row + 8) * ldc + col) = make_float2(v2, v3);
        }
    }
}

// ---------------- split-K reduce for GEMM2 -> xdbl + fused dt split ----------------
__global__ void __launch_bounds__(256)
reduce4(const float* __restrict__ part, float* __restrict__ xdbl,
        __nv_bfloat16* __restrict__ dth, __nv_bfloat16* __restrict__ dtl)
{
    const int i = blockIdx.x * 256 + threadIdx.x;
    if (i >= MM * XDBL_W) return;
    const int r = i / XDBL_W, c = i - r * XDBL_W;
    const size_t o = (size_t)r * 128 + c;
    float s = part[o] + part[o + (size_t)MM * 128]
            + part[o + (size_t)2 * MM * 128] + part[o + (size_t)3 * MM * 128];
    xdbl[i] = s;
    if (c < DTR) {
        __nv_bfloat16 h, l;
        bf16split(s, h, l);
        dth[(size_t)r * DTR + c] = h;
        dtl[(size_t)r * DTR + c] = l;
    }
}

// ---------------- weight transpose + bf16 split: W(K,N) -> Th/Tl (N,K) ----------------
__global__ void __launch_bounds__(256)
tsplit(const float* __restrict__ W, __nv_bfloat16* __restrict__ Th, __nv_bfloat16* __restrict__ Tl,
       int K, int N)
{
    __shared__ float t[32][33];
    const int n0 = blockIdx.x * 32;
    const int k0 = blockIdx.y * 32;
    const int tx = threadIdx.x & 31;
    const int ty = threadIdx.x >> 5;
    #pragma unroll
    for (int i = 0; i < 32; i += 8)
        t[ty + i][tx] = W[(size_t)(k0 + ty + i) * N + (n0 + tx)];
    __syncthreads();
    #pragma unroll
    for (int i = 0; i < 32; i += 8) {
        __nv_bfloat16 h, l;
        bf16split(t[tx][ty + i], h, l);
        Th[(size_t)(n0 + ty + i) * K + (k0 + tx)] = h;
        Tl[(size_t)(n0 + ty + i) * K + (k0 + tx)] = l;
    }
}

// ---------------- fp32 -> bf16 hi/lo split (dense) ----------------
__global__ void __launch_bounds__(256)
split_plain(const float* __restrict__ in, __nv_bfloat16* __restrict__ h,
            __nv_bfloat16* __restrict__ l, int n4)
{
    const int i = blockIdx.x * blockDim.x + threadIdx.x;
    if (i >= n4) return;
    const float4 v = ((const float4*)in)[i];
    __nv_bfloat16 hh[4], ll[4];
    bf16split(v.x, hh[0], ll[0]);
    bf16split(v.y, hh[1], ll[1]);
    bf16split(v.z, hh[2], ll[2]);
    bf16split(v.w, hh[3], ll[3]);
    ((uint2*)h)[i] = make_uint2(
        (uint32_t)__bfloat16_as_ushort(hh[0]) | ((uint32_t)__bfloat16_as_ushort(hh[1]) << 16),
        (uint32_t)__bfloat16_as_ushort(hh[2]) | ((uint32_t)__bfloat16_as_ushort(hh[3]) << 16));
    ((uint2*)l)[i] = make_uint2(
        (uint32_t)__bfloat16_as_ushort(ll[0]) | ((uint32_t)__bfloat16_as_ushort(ll[1]) << 16),
        (uint32_t)__bfloat16_as_ushort(ll[2]) | ((uint32_t)__bfloat16_as_ushort(ll[3]) << 16));
}

// ---------------- causal depthwise conv (k=4) + SiLU, fused bf16 split ----------------
__global__ void __launch_bounds__(256)
conv_silu_kernel(const float* __restrict__ xr, const float* __restrict__ w,
                 const float* __restrict__ bias, float* __restrict__ out,
                 __nv_bfloat16* __restrict__ oh, __nv_bfloat16* __restrict__ ol)
{
    const int idx = blockIdx.x * blockDim.x + threadIdx.x;
    if (idx >= MM * DI) return;
    const int d = idx & (DI - 1);
    const int m = idx >> 11;
    const int l = m & (LL - 1);
    const int b = m >> 11;

    float acc = bias[d];
    #pragma unroll
    for (int i = 0; i < DC; i++) {
        const int lp = l + i - (DC - 1);
        if (lp >= 0)
            acc = fmaf(xr[((size_t)(b * LL + lp)) * (2 * DI) + d], w[d * DC + i], acc);
    }
    const float v = acc * (1.0f / (1.0f + __expf(-acc)));
    out[idx] = v;
    __nv_bfloat16 hh, ll;
    bf16split(v, hh, ll);
    oh[idx] = hh; ol[idx] = ll;
}

// ---------------- chunked selective scan: pass 1 (chunk-local h and prod dA) ----------------
__global__ void __launch_bounds__(256)
scan_p1(const float* __restrict__ dt, const float* __restrict__ u,
        const float* __restrict__ xdbl, const float* __restrict__ logA,
        float* __restrict__ H, float* __restrict__ P)
{
    const int idx = blockIdx.x * 256 + threadIdx.x;      // 65536
    const int d = idx & (DI - 1);
    const int t = idx >> 11;
    const int c = t & (NCH - 1);
    const int b = t >> 3;

    float A[DS];
    #pragma unroll
    for (int n = 0; n < DS; n++) A[n] = -__expf(logA[d * DS + n]);
    const float A0 = A[0];
    bool pw = true;
    #pragma unroll
    for (int n = 1; n < DS; n++)
        pw = pw && (fabsf(A[n] - (float)(n + 1) * A0) <= 1e-5f * fabsf(A[n]));

    float h[DS], Pr[DS];
    #pragma unroll
    for (int n = 0; n < DS; n++) { h[n] = 0.0f; Pr[n] = 1.0f; }

    const int l0 = c * CL;
    for (int l = l0; l < l0 + CL; l++) {
        const size_t m = (size_t)b * LL + l;
        const float dtv = dt[m * DI + d];
        const float uv  = u[m * DI + d];
        const float dtu = dtv * uv;

        float e[DS];
        if (pw) {
            const float e1 = __expf(dtv * A0);
            float p = e1;
            e[0] = p;
            #pragma unroll
            for (int n = 1; n < DS; n++) { p *= e1; e[n] = p; }
        } else {
            #pragma unroll
            for (int n = 0; n < DS; n++) e[n] = __expf(dtv * A[n]);
        }

        const float4* bp = (const float4*)(xdbl + m * XDBL_W + DTR);
        float Bv[DS];
        #pragma unroll
        for (int q = 0; q < 4; q++) {
            const float4 v = bp[q];
            Bv[q*4+0]=v.x; Bv[q*4+1]=v.y; Bv[q*4+2]=v.z; Bv[q*4+3]=v.w;
        }
        #pragma unroll
        for (int n = 0; n < DS; n++) {
            h[n] = fmaf(e[n], h[n], dtu * Bv[n]);
            Pr[n] *= e[n];
        }
    }
    const size_t o = ((size_t)(b * NCH + c) * DS) * DI + d;
    #pragma unroll
    for (int n = 0; n < DS; n++) { H[o + (size_t)n * DI] = h[n]; P[o + (size_t)n * DI] = Pr[n]; }
}

// ---------------- chunked scan: pass 2 (recombine + y + gate + bf16 split) ----------------
__global__ void __launch_bounds__(256)
scan_p2(const float* __restrict__ dt, const float* __restrict__ u,
        const float* __restrict__ xdbl, const float* __restrict__ logA,
        const float* __restrict__ Dp, const float* __restrict__ xr,
        const float* __restrict__ H, const float* __restrict__ P,
        __nv_bfloat16* __restrict__ ygh, __nv_bfloat16* __restrict__ ygl)
{
    const int idx = blockIdx.x * 256 + threadIdx.x;
    const int d = idx & (DI - 1);
    const int t = idx >> 11;
    const int c = t & (NCH - 1);
    const int b = t >> 3;

    float A[DS];
    #pragma unroll
    for (int n = 0; n < DS; n++) A[n] = -__expf(logA[d * DS + n]);
    const float A0 = A[0];
    bool pw = true;
    #pragma unroll
    for (int n = 1; n < DS; n++)
        pw = pw && (fabsf(A[n] - (float)(n + 1) * A0) <= 1e-5f * fabsf(A[n]));

    // recombine preceding chunk states
    float h[DS];
    #pragma unroll
    for (int n = 0; n < DS; n++) h[n] = 0.0f;
    for (int j = 0; j < c; j++) {
        const size_t o = ((size_t)(b * NCH + j) * DS) * DI + d;
        #pragma unroll
        for (int n = 0; n < DS; n++)
            h[n] = fmaf(P[o + (size_t)n * DI], h[n], H[o + (size_t)n * DI]);
    }
    const float Dv = Dp[d];

    const int l0 = c * CL;
    for (int l = l0; l < l0 + CL; l++) {
        const size_t m = (size_t)b * LL + l;
        const float dtv = dt[m * DI + d];
        const float uv  = u[m * DI + d];
        const float dtu = dtv * uv;

        float e[DS];
        if (pw) {
            const float e1 = __expf(dtv * A0);
            float p = e1;
            e[0] = p;
            #pragma unroll
            for (int n = 1; n < DS; n++) { p *= e1; e[n] = p; }
        } else {
            #pragma unroll
            for (int n = 0; n < DS; n++) e[n] = __expf(dtv * A[n]);
        }

        const float4* bp = (const float4*)(xdbl + m * XDBL_W + DTR);
        float Bv[DS], Cv[DS];
        #pragma unroll
        for (int q = 0; q < 4; q++) {
            const float4 v = bp[q];
            Bv[q*4+0]=v.x; Bv[q*4+1]=v.y; Bv[q*4+2]=v.z; Bv[q*4+3]=v.w;
        }
        #pragma unroll
        for (int q = 0; q < 4; q++) {
            const float4 v = bp[4 + q];
            Cv[q*4+0]=v.x; Cv[q*4+1]=v.y; Cv[q*4+2]=v.z; Cv[q*4+3]=v.w;
        }

        float y = 0.0f;
        #pragma unroll
        for (int n = 0; n < DS; n++) {
            h[n] = fmaf(e[n], h[n], dtu * Bv[n]);
            y = fmaf(Cv[n], h[n], y);
        }
        y = fmaf(Dv, uv, y);

        const float r = xr[m * (2 * DI) + DI + d];
        const float g = r * (1.0f / (1.0f + __expf(-r)));
        const float yg = y * g;
        __nv_bfloat16 hh, ll;
        bf16split(yg, hh, ll);
        ygh[m * DI + d] = hh;
        ygl[m * DI + d] = ll;
    }
}

// ---------------- host launcher ----------------
extern "C" void kernel_launch(void* const* d_in, const int* in_sizes, int n_in,
                              void* d_out, int out_size)
{
    const float* x      = (const float*)d_in[0];
    const float* W_in   = (const float*)d_in[1];
    const float* conv_w = (const float*)d_in[2];
    const float* conv_b = (const float*)d_in[3];
    const float* W_x    = (const float*)d_in[4];
    const float* W_dt   = (const float*)d_in[5];
    const float* b_dt   = (const float*)d_in[6];
    const float* logA   = (const float*)d_in[7];
    const float* Dp     = (const float*)d_in[8];
    const float* W_out  = (const float*)d_in[9];
    float* out = (float*)d_out;

    // smem: big variant 2*(2*256*128 + 2*16384) = 196608; small = 131072
    cudaFuncSetAttribute(hgemm<256,64>, cudaFuncAttributeMaxDynamicSharedMemorySize, 196608);
    cudaFuncSetAttribute(hgemm<128,32>, cudaFuncAttributeMaxDynamicSharedMemorySize, 131072);

    float *xr, *xval, *xdbl, *dtb, *Hb, *Pb, *part;
    cudaGetSymbolAddress((void**)&xr,   g_xr);
    cudaGetSymbolAddress((void**)&xval, g_xval);
    cudaGetSymbolAddress((void**)&xdbl, g_xdbl);
    cudaGetSymbolAddress((void**)&dtb,  g_dt);
    cudaGetSymbolAddress((void**)&Hb,   g_H);
    cudaGetSymbolAddress((void**)&Pb,   g_P);
    cudaGetSymbolAddress((void**)&part, g_part);

    __nv_bfloat16 *xh, *xl, *xvh, *xvl, *dth, *dtl, *ygh, *ygl;
    cudaGetSymbolAddress((void**)&xh,  g_xh);
    cudaGetSymbolAddress((void**)&xl,  g_xl);
    cudaGetSymbolAddress((void**)&xvh, g_xvh);
    cudaGetSymbolAddress((void**)&xvl, g_xvl);
    cudaGetSymbolAddress((void**)&dth, g_dth);
    cudaGetSymbolAddress((void**)&dtl, g_dtl);
    cudaGetSymbolAddress((void**)&ygh, g_ygh);
    cudaGetSymbolAddress((void**)&ygl, g_ygl);

    __nv_bfloat16 *winh, *winl, *wxh, *wxl, *wdth, *wdtl, *wouth, *woutl;
    cudaGetSymbolAddress((void**)&winh,  g_winT_h);
    cudaGetSymbolAddress((void**)&winl,  g_winT_l);
    cudaGetSymbolAddress((void**)&wxh,   g_wxT_h);
    cudaGetSymbolAddress((void**)&wxl,   g_wxT_l);
    cudaGetSymbolAddress((void**)&wdth,  g_wdtT_h);
    cudaGetSymbolAddress((void**)&wdtl,  g_wdtT_l);
    cudaGetSymbolAddress((void**)&wouth, g_woutT_h);
    cudaGetSymbolAddress((void**)&woutl, g_woutT_l);

    // weight prep: transpose + split
    tsplit<<<dim3((2*DI)/32, DM/32), 256>>>(W_in, winh, winl, DM, 2*DI);
    tsplit<<<dim3(XDBL_W/32, DI/32), 256>>>(W_x, wxh, wxl, DI, XDBL_W);
    tsplit<<<dim3(DI/32, DTR/32), 256>>>(W_dt, wdth, wdtl, DTR, DI);
    tsplit<<<dim3(DM/32, DI/32), 256>>>(W_out, wouth, woutl, DI, DM);

    // split x
    split_plain<<<(MM*DM/4 + 255)/256, 256>>>(x, xh, xl, MM*DM/4);

    // 1) x @ W_in -> xr (8192 x 4096)   [CTAM=256, grid 32x32=1024]
    hgemm<256,64><<<dim3((2*DI)/128, MM/256), 256, 196608>>>(
        xh, xl, winh, winl, xr, 2*DI, DM, 2*DI, nullptr, 0, DM, 0);

    // 2) causal conv + silu -> xval fp32 + hi/lo
    conv_silu_kernel<<<(MM*DI + 255)/256, 256>>>(xr, conv_w, conv_b, xval, xvh, xvl);

    // 3) xval @ W_x -> partials (split-K=4), then reduce -> xdbl + dt split
    hgemm<128,32><<<dim3(1, MM/128, 4), 256, 131072>>>(
        xvh, xvl, wxh, wxl, part, 128, DI, 128, nullptr, 0, DI/4, (size_t)MM*128);
    reduce4<<<(MM*XDBL_W + 255)/256, 256>>>(part, xdbl, dth, dtl);

    // 4) softplus(dt_in @ W_dt + b_dt) -> dt (8192 x 2048), K=64
    hgemm<128,32><<<dim3(DI/128, MM/128), 256, 131072>>>(
        dth, dtl, wdth, wdtl, dtb, DI, DTR, DI, b_dt, 1, DTR, 0);

    // 5) chunked selective scan
    scan_p1<<<(BB*DI*NCH)/256, 256>>>(dtb, xval, xdbl, logA, Hb, Pb);
    scan_p2<<<(BB*DI*NCH)/256, 256>>>(dtb, xval, xdbl, logA, Dp, xr, Hb, Pb, ygh, ygl);

    // 6) yg @ W_out -> out (8192 x 1024)  [grid 8x64=512]
    hgemm<128,32><<<dim3(DM/128, MM/128), 256, 131072>>>(
        ygh, ygl, wouth, woutl, out, DM, DI, DM, nullptr, 0, DI, 0);
}

// round 5
// speedup vs baseline: 4.7015x; 1.4267x over previous
#include <cuda_runtime.h>
#include <cuda_bf16.h>
#include <cuda_fp16.h>
#include <cstdint>

// Problem constants
#define BB 4
#define LL 2048
#define DM 1024
#define DI 2048        // D_INNER
#define DS 16          // D_STATE
#define DC 4           // D_CONV
#define DTR 64         // DT_RANK
#define MM (BB*LL)     // 8192 rows
#define XDBL_W (DTR + 2*DS)   // 96
#define NCH 8          // scan chunks
#define CL (LL/NCH)    // 256 steps per chunk

// ---------------- scratch (static device globals; no allocations) ----------------
__device__ __align__(16) float g_xr[(size_t)MM * (2*DI)];     // x_and_res
__device__ __align__(16) float g_xdbl[(size_t)MM * XDBL_W];   // dt_in | B | C
__device__ __align__(16) float g_dt[(size_t)MM * DI];         // softplus dt
__device__ __align__(16) float g_H[(size_t)BB * NCH * DS * DI];  // chunk-local final h
__device__ __align__(16) float g_P[(size_t)BB * NCH * DS * DI];  // chunk prod(dA)
__device__ __align__(16) float g_part[(size_t)4 * MM * 128];     // split-K partials (GEMM2)

// fp16 activations, row-major M x K
__device__ __align__(16) __half g_xh [(size_t)MM * DM];
__device__ __align__(16) __half g_xvh[(size_t)MM * DI];       // conv+silu output (u)
__device__ __align__(16) __half g_dth[(size_t)MM * DTR];
__device__ __align__(16) __half g_ygh[(size_t)MM * DI];

// transposed fp16 weights, layout (N, K) row-major
__device__ __align__(16) __half g_winT[(size_t)(2*DI) * DM];
__device__ __align__(16) __half g_wxT[(size_t)128 * DI];      // rows 96..127 stay zero
__device__ __align__(16) __half g_wdtT[(size_t)DI * DTR];
__device__ __align__(16) __half g_woutT[(size_t)DM * DI];

// ===================== low-level helpers =====================
__device__ __forceinline__ uint32_t smem_u32(const void* p) {
    uint32_t a;
    asm("{ .reg .u64 t; cvta.to.shared.u64 t, %1; cvt.u32.u64 %0, t; }" : "=r"(a) : "l"(p));
    return a;
}
__device__ __forceinline__ void cpa16(uint32_t s, const void* g) {
    asm volatile("cp.async.cg.shared.global [%0], [%1], 16;" :: "r"(s), "l"(g));
}
#define CP_COMMIT() asm volatile("cp.async.commit_group;")
#define CP_WAIT(n)  asm volatile("cp.async.wait_group %0;" :: "n"(n))

__device__ __forceinline__ void ldsm4(uint32_t* r, uint32_t addr) {
    asm volatile("ldmatrix.sync.aligned.m8n8.x4.shared.b16 {%0,%1,%2,%3}, [%4];"
        : "=r"(r[0]), "=r"(r[1]), "=r"(r[2]), "=r"(r[3]) : "r"(addr));
}
__device__ __forceinline__ void mma16816(float* d, const uint32_t* a, const uint32_t* b) {
    asm volatile(
        "mma.sync.aligned.m16n8k16.row.col.f32.f16.f16.f32 "
        "{%0,%1,%2,%3}, {%4,%5,%6,%7}, {%8,%9}, {%0,%1,%2,%3};"
        : "+f"(d[0]), "+f"(d[1]), "+f"(d[2]), "+f"(d[3])
        : "r"(a[0]), "r"(a[1]), "r"(a[2]), "r"(a[3]), "r"(b[0]), "r"(b[1]));
}

// ================= HMMA GEMM: C(M,N=128/CTA) = A(M,K) @ B(N,K)^T, fp16 single-term =================
// CTAM x 128 CTA tile, BK=64, 8 warps; warp tile 64 x WN.
// CTAM=256 -> WN=64 (warps 4Mx2N); CTAM=128 -> WN=32 (warps 2Mx4N).
template<int CTAM, int WN>
__global__ void __launch_bounds__(256, 1)
hgemm(const __half* __restrict__ A, const __half* __restrict__ B,
      float* __restrict__ C, int N, int K, int ldc,
      const float* __restrict__ bias, int epi, int kslice, size_t zstride)
{
    constexpr int MW  = CTAM / 64;      // warps along M
    constexpr int G   = WN / 16;        // n16 groups per warp
    constexpr int NJ  = WN / 8;         // n8 frags per warp
    constexpr int ASZ = CTAM * 128;     // bytes of A per stage (64 cols x 2B)
    constexpr int BSZ = 16384;          // bytes of B per stage
    constexpr int STAGE = ASZ + BSZ;

    extern __shared__ char smem[];
    const uint32_t sb = smem_u32(smem);
    const int tid  = threadIdx.x;
    const int wid  = tid >> 5;
    const int lane = tid & 31;
    const int row0 = blockIdx.y * CTAM;
    const int col0 = blockIdx.x * 128;
    const int wm = wid & (MW - 1);
    const int wn = wid / MW;

    const int kbase = blockIdx.z * kslice;
    C += (size_t)blockIdx.z * zstride;
    const int KT = kslice >> 6;

    float acc[4][NJ][4];
    #pragma unroll
    for (int i = 0; i < 4; i++)
        #pragma unroll
        for (int j = 0; j < NJ; j++)
            #pragma unroll
            for (int q = 0; q < 4; q++) acc[i][j][q] = 0.0f;

    auto load_stage = [&](int s, int k0) {
        const uint32_t base = sb + (uint32_t)s * STAGE;
        #pragma unroll
        for (int i = 0; i < CTAM / 32; i++) {
            const int lin = tid + i * 256;
            const int r = lin >> 3, c = lin & 7;
            const uint32_t so = (uint32_t)(r * 128 + ((c ^ (r & 7)) << 4));
            cpa16(base + so, A + (size_t)(row0 + r) * K + k0 + c * 8);
        }
        #pragma unroll
        for (int i = 0; i < 4; i++) {
            const int lin = tid + i * 256;
            const int r = lin >> 3, c = lin & 7;
            const uint32_t so = (uint32_t)(r * 128 + ((c ^ (r & 7)) << 4));
            cpa16(base + ASZ + so, B + (size_t)(col0 + r) * K + k0 + c * 8);
        }
        CP_COMMIT();
    };

    auto compute_stage = [&](int s) {
        const uint32_t aBase = sb + (uint32_t)s * STAGE;
        const uint32_t bBase = aBase + ASZ;
        #pragma unroll
        for (int ks = 0; ks < 4; ks++) {
            uint32_t ah[4][4];
            #pragma unroll
            for (int mt = 0; mt < 4; mt++) {
                const int R = wm * 64 + mt * 16 + (lane & 15);
                const int c = ks * 2 + (lane >> 4);
                ldsm4(ah[mt], aBase + (uint32_t)(R * 128 + ((c ^ (R & 7)) << 4)));
            }
            #pragma unroll
            for (int g = 0; g < G; g++) {
                const int R = wn * WN + g * 16 + (lane & 7) + ((lane >> 4) & 1) * 8;
                const int c = ks * 2 + ((lane >> 3) & 1);
                uint32_t bh[4];
                ldsm4(bh, bBase + (uint32_t)(R * 128 + ((c ^ (R & 7)) << 4)));
                #pragma unroll
                for (int mt = 0; mt < 4; mt++)
                    #pragma unroll
                    for (int sub = 0; sub < 2; sub++)
                        mma16816(acc[mt][g * 2 + sub], ah[mt], &bh[sub * 2]);
            }
        }
    };

    load_stage(0, kbase);
    for (int kt = 0; kt < KT; kt++) {
        if (kt + 1 < KT) {
            load_stage((kt + 1) & 1, kbase + (kt + 1) * 64);
            CP_WAIT(1);
        } else {
            CP_WAIT(0);
        }
        __syncthreads();
        compute_stage(kt & 1);
        __syncthreads();
    }

    // ---- epilogue ----
    #pragma unroll
    for (int mt = 0; mt < 4; mt++) {
        const int row = row0 + wm * 64 + mt * 16 + (lane >> 2);
        #pragma unroll
        for (int j = 0; j < NJ; j++) {
            const int col = col0 + wn * WN + j * 8 + (lane & 3) * 2;
            float v0 = acc[mt][j][0], v1 = acc[mt][j][1];
            float v2 = acc[mt][j][2], v3 = acc[mt][j][3];
            if (epi == 1) {
                const float b0 = bias[col], b1 = bias[col + 1];
                v0 += b0; v0 = (v0 > 20.0f) ? v0 : log1pf(__expf(v0));
                v1 += b1; v1 = (v1 > 20.0f) ? v1 : log1pf(__expf(v1));
                v2 += b0; v2 = (v2 > 20.0f) ? v2 : log1pf(__expf(v2));
                v3 += b1; v3 = (v3 > 20.0f) ? v3 : log1pf(__expf(v3));
            }
            *(float2*)(C + (size_t)row * ldc + col)       = make_float2(v0, v1);
            *(float2*)(C + (size_t)(row + 8) * ldc + col) = make_float2(v2, v3);
        }
    }
}

// ---------------- split-K reduce for GEMM2 -> xdbl + fused dt fp16 ----------------
__global__ void __launch_bounds__(256)
reduce4(const float* __restrict__ part, float* __restrict__ xdbl, __half* __restrict__ dth)
{
    const int i = blockIdx.x * 256 + threadIdx.x;
    if (i >= MM * XDBL_W) return;
    const int r = i / XDBL_W, c = i - r * XDBL_W;
    const size_t o = (size_t)r * 128 + c;
    float s = part[o] + part[o + (size_t)MM * 128]
            + part[o + (size_t)2 * MM * 128] + part[o + (size_t)3 * MM * 128];
    xdbl[i] = s;
    if (c < DTR) dth[(size_t)r * DTR + c] = __float2half_rn(s);
}

// ---------------- weight transpose -> fp16: W(K,N) -> T(N,K) ----------------
__global__ void __launch_bounds__(256)
ttrans(const float* __restrict__ W, __half* __restrict__ T, int K, int N)
{
    __shared__ float t[32][33];
    const int n0 = blockIdx.x * 32;
    const int k0 = blockIdx.y * 32;
    const int tx = threadIdx.x & 31;
    const int ty = threadIdx.x >> 5;
    #pragma unroll
    for (int i = 0; i < 32; i += 8)
        t[ty + i][tx] = W[(size_t)(k0 + ty + i) * N + (n0 + tx)];
    __syncthreads();
    #pragma unroll
    for (int i = 0; i < 32; i += 8)
        T[(size_t)(n0 + ty + i) * K + (k0 + tx)] = __float2half_rn(t[tx][ty + i]);
}

// ---------------- fp32 -> fp16 (dense) ----------------
__global__ void __launch_bounds__(256)
to_half(const float* __restrict__ in, __half* __restrict__ h, int n4)
{
    const int i = blockIdx.x * blockDim.x + threadIdx.x;
    if (i >= n4) return;
    const float4 v = ((const float4*)in)[i];
    __half2 a = __floats2half2_rn(v.x, v.y);
    __half2 b = __floats2half2_rn(v.z, v.w);
    ((uint2*)h)[i] = make_uint2(*(uint32_t*)&a, *(uint32_t*)&b);
}

// ---------------- causal depthwise conv (k=4) + SiLU -> fp16 ----------------
__global__ void __launch_bounds__(256)
conv_silu_kernel(const float* __restrict__ xr, const float* __restrict__ w,
                 const float* __restrict__ bias, __half* __restrict__ oh)
{
    const int idx = blockIdx.x * blockDim.x + threadIdx.x;
    if (idx >= MM * DI) return;
    const int d = idx & (DI - 1);
    const int m = idx >> 11;
    const int l = m & (LL - 1);
    const int b = m >> 11;

    float acc = bias[d];
    #pragma unroll
    for (int i = 0; i < DC; i++) {
        const int lp = l + i - (DC - 1);
        if (lp >= 0)
            acc = fmaf(xr[((size_t)(b * LL + lp)) * (2 * DI) + d], w[d * DC + i], acc);
    }
    const float v = acc * (1.0f / (1.0f + __expf(-acc)));
    oh[idx] = __float2half_rn(v);
}

// ---------------- chunked selective scan: pass 1 (chunk-local h and prod dA) ----------------
__global__ void __launch_bounds__(256)
scan_p1(const float* __restrict__ dt, const __half* __restrict__ u,
        const float* __restrict__ xdbl, const float* __restrict__ logA,
        float* __restrict__ H, float* __restrict__ P)
{
    const int idx = blockIdx.x * 256 + threadIdx.x;      // 65536
    const int d = idx & (DI - 1);
    const int t = idx >> 11;
    const int c = t & (NCH - 1);
    const int b = t >> 3;

    float A[DS];
    #pragma unroll
    for (int n = 0; n < DS; n++) A[n] = -__expf(logA[d * DS + n]);
    const float A0 = A[0];
    bool pw = true;
    #pragma unroll
    for (int n = 1; n < DS; n++)
        pw = pw && (fabsf(A[n] - (float)(n + 1) * A0) <= 1e-5f * fabsf(A[n]));

    float h[DS], Pr[DS];
    #pragma unroll
    for (int n = 0; n < DS; n++) { h[n] = 0.0f; Pr[n] = 1.0f; }

    const int l0 = c * CL;
    for (int l = l0; l < l0 + CL; l++) {
        const size_t m = (size_t)b * LL + l;
        const float dtv = dt[m * DI + d];
        const float uv  = __half2float(u[m * DI + d]);
        const float dtu = dtv * uv;

        float e[DS];
        if (pw) {
            const float e1 = __expf(dtv * A0);
            float p = e1;
            e[0] = p;
            #pragma unroll
            for (int n = 1; n < DS; n++) { p *= e1; e[n] = p; }
        } else {
            #pragma unroll
            for (int n = 0; n < DS; n++) e[n] = __expf(dtv * A[n]);
        }

        const float4* bp = (const float4*)(xdbl + m * XDBL_W + DTR);
        float Bv[DS];
        #pragma unroll
        for (int q = 0; q < 4; q++) {
            const float4 v = bp[q];
            Bv[q*4+0]=v.x; Bv[q*4+1]=v.y; Bv[q*4+2]=v.z; Bv[q*4+3]=v.w;
        }
        #pragma unroll
        for (int n = 0; n < DS; n++) {
            h[n] = fmaf(e[n], h[n], dtu * Bv[n]);
            Pr[n] *= e[n];
        }
    }
    const size_t o = ((size_t)(b * NCH + c) * DS) * DI + d;
    #pragma unroll
    for (int n = 0; n < DS; n++) { H[o + (size_t)n * DI] = h[n]; P[o + (size_t)n * DI] = Pr[n]; }
}

// ---------------- chunked scan: pass 2 (recombine + y + gate -> fp16) ----------------
__global__ void __launch_bounds__(256)
scan_p2(const float* __restrict__ dt, const __half* __restrict__ u,
        const float* __restrict__ xdbl, const float* __restrict__ logA,
        const float* __restrict__ Dp, const float* __restrict__ xr,
        const float* __restrict__ H, const float* __restrict__ P,
        __half* __restrict__ ygh)
{
    const int idx = blockIdx.x * 256 + threadIdx.x;
    const int d = idx & (DI - 1);
    const int t = idx >> 11;
    const int c = t & (NCH - 1);
    const int b = t >> 3;

    float A[DS];
    #pragma unroll
    for (int n = 0; n < DS; n++) A[n] = -__expf(logA[d * DS + n]);
    const float A0 = A[0];
    bool pw = true;
    #pragma unroll
    for (int n = 1; n < DS; n++)
        pw = pw && (fabsf(A[n] - (float)(n + 1) * A0) <= 1e-5f * fabsf(A[n]));

    // recombine preceding chunk states
    float h[DS];
    #pragma unroll
    for (int n = 0; n < DS; n++) h[n] = 0.0f;
    for (int j = 0; j < c; j++) {
        const size_t o = ((size_t)(b * NCH + j) * DS) * DI + d;
        #pragma unroll
        for (int n = 0; n < DS; n++)
            h[n] = fmaf(P[o + (size_t)n * DI], h[n], H[o + (size_t)n * DI]);
    }
    const float Dv = Dp[d];

    const int l0 = c * CL;
    for (int l = l0; l < l0 + CL; l++) {
        const size_t m = (size_t)b * LL + l;
        const float dtv = dt[m * DI + d];
        const float uv  = __half2float(u[m * DI + d]);
        const float dtu = dtv * uv;

        float e[DS];
        if (pw) {
            const float e1 = __expf(dtv * A0);
            float p = e1;
            e[0] = p;
            #pragma unroll
            for (int n = 1; n < DS; n++) { p *= e1; e[n] = p; }
        } else {
            #pragma unroll
            for (int n = 0; n < DS; n++) e[n] = __expf(dtv * A[n]);
        }

        const float4* bp = (const float4*)(xdbl + m * XDBL_W + DTR);
        float Bv[DS], Cv[DS];
        #pragma unroll
        for (int q = 0; q < 4; q++) {
            const float4 v = bp[q];
            Bv[q*4+0]=v.x; Bv[q*4+1]=v.y; Bv[q*4+2]=v.z; Bv[q*4+3]=v.w;
        }
        #pragma unroll
        for (int q = 0; q < 4; q++) {
            const float4 v = bp[4 + q];
            Cv[q*4+0]=v.x; Cv[q*4+1]=v.y; Cv[q*4+2]=v.z; Cv[q*4+3]=v.w;
        }

        float y = 0.0f;
        #pragma unroll
        for (int n = 0; n < DS; n++) {
            h[n] = fmaf(e[n], h[n], dtu * Bv[n]);
            y = fmaf(Cv[n], h[n], y);
        }
        y = fmaf(Dv, uv, y);

        const float r = xr[m * (2 * DI) + DI + d];
        const float g = r * (1.0f / (1.0f + __expf(-r)));
        ygh[m * DI + d] = __float2half_rn(y * g);
    }
}

// ---------------- host launcher ----------------
extern "C" void kernel_launch(void* const* d_in, const int* in_sizes, int n_in,
                              void* d_out, int out_size)
{
    const float* x      = (const float*)d_in[0];
    const float* W_in   = (const float*)d_in[1];
    const float* conv_w = (const float*)d_in[2];
    const float* conv_b = (const float*)d_in[3];
    const float* W_x    = (const float*)d_in[4];
    const float* W_dt   = (const float*)d_in[5];
    const float* b_dt   = (const float*)d_in[6];
    const float* logA   = (const float*)d_in[7];
    const float* Dp     = (const float*)d_in[8];
    const float* W_out  = (const float*)d_in[9];
    float* out = (float*)d_out;

    // smem: CTAM=256 variant 2*(256*128 + 16384) = 98304; CTAM=128 variant 65536
    cudaFuncSetAttribute(hgemm<256,64>, cudaFuncAttributeMaxDynamicSharedMemorySize, 98304);
    cudaFuncSetAttribute(hgemm<128,32>, cudaFuncAttributeMaxDynamicSharedMemorySize, 65536);

    float *xr, *xdbl, *dtb, *Hb, *Pb, *part;
    cudaGetSymbolAddress((void**)&xr,   g_xr);
    cudaGetSymbolAddress((void**)&xdbl, g_xdbl);
    cudaGetSymbolAddress((void**)&dtb,  g_dt);
    cudaGetSymbolAddress((void**)&Hb,   g_H);
    cudaGetSymbolAddress((void**)&Pb,   g_P);
    cudaGetSymbolAddress((void**)&part, g_part);

    __half *xh, *xvh, *dth, *ygh;
    cudaGetSymbolAddress((void**)&xh,  g_xh);
    cudaGetSymbolAddress((void**)&xvh, g_xvh);
    cudaGetSymbolAddress((void**)&dth, g_dth);
    cudaGetSymbolAddress((void**)&ygh, g_ygh);

    __half *winT, *wxT, *wdtT, *woutT;
    cudaGetSymbolAddress((void**)&winT,  g_winT);
    cudaGetSymbolAddress((void**)&wxT,   g_wxT);
    cudaGetSymbolAddress((void**)&wdtT,  g_wdtT);
    cudaGetSymbolAddress((void**)&woutT, g_woutT);

    // weight prep: transpose -> fp16
    ttrans<<<dim3((2*DI)/32, DM/32), 256>>>(W_in, winT, DM, 2*DI);
    ttrans<<<dim3(XDBL_W/32, DI/32), 256>>>(W_x, wxT, DI, XDBL_W);
    ttrans<<<dim3(DI/32, DTR/32), 256>>>(W_dt, wdtT, DTR, DI);
    ttrans<<<dim3(DM/32, DI/32), 256>>>(W_out, woutT, DI, DM);

    // x -> fp16
    to_half<<<(MM*DM/4 + 255)/256, 256>>>(x, xh, MM*DM/4);

    // 1) x @ W_in -> xr (8192 x 4096)   [CTAM=256, grid 32x32]
    hgemm<256,64><<<dim3((2*DI)/128, MM/256), 256, 98304>>>(
        xh, winT, xr, 2*DI, DM, 2*DI, nullptr, 0, DM, 0);

    // 2) causal conv + silu -> xvh (fp16)
    conv_silu_kernel<<<(MM*DI + 255)/256, 256>>>(xr, conv_w, conv_b, xvh);

    // 3) xval @ W_x -> partials (split-K=4), then reduce -> xdbl + dt fp16
    hgemm<128,32><<<dim3(1, MM/128, 4), 256, 65536>>>(
        xvh, wxT, part, 128, DI, 128, nullptr, 0, DI/4, (size_t)MM*128);
    reduce4<<<(MM*XDBL_W + 255)/256, 256>>>(part, xdbl, dth);

    // 4) softplus(dt_in @ W_dt + b_dt) -> dt (8192 x 2048), K=64
    hgemm<128,32><<<dim3(DI/128, MM/128), 256, 65536>>>(
        dth, wdtT, dtb, DI, DTR, DI, b_dt, 1, DTR, 0);

    // 5) chunked selective scan
    scan_p1<<<(BB*DI*NCH)/256, 256>>>(dtb, xvh, xdbl, logA, Hb, Pb);
    scan_p2<<<(BB*DI*NCH)/256, 256>>>(dtb, xvh, xdbl, logA, Dp, xr, Hb, Pb, ygh);

    // 6) yg @ W_out -> out (8192 x 1024)
    hgemm<128,32><<<dim3(DM/128, MM/128), 256, 65536>>>(
        ygh, woutT, out, DM, DI, DM, nullptr, 0, DI, 0);
}

// round 6
// speedup vs baseline: 4.9798x; 1.0592x over previous
#include <cuda_runtime.h>
#include <cuda_bf16.h>
#include <cuda_fp16.h>
#include <cstdint>

// Problem constants
#define BB 4
#define LL 2048
#define DM 1024
#define DI 2048        // D_INNER
#define DS 16          // D_STATE
#define DC 4           // D_CONV
#define DTR 64         // DT_RANK
#define MM (BB*LL)     // 8192 rows
#define XDBL_W (DTR + 2*DS)   // 96
#define NCH 8          // scan chunks
#define CL (LL/NCH)    // 256 steps per chunk

// ---------------- scratch (static device globals; no allocations) ----------------
__device__ __align__(16) float g_xr[(size_t)MM * (2*DI)];     // x_and_res
__device__ __align__(16) float g_xdbl[(size_t)MM * XDBL_W];   // dt_in | B | C
__device__ __align__(16) float g_dt[(size_t)MM * DI];         // softplus dt
__device__ __align__(16) float g_H[(size_t)BB * NCH * DS * DI];  // chunk-local final h
__device__ __align__(16) float g_P[(size_t)BB * NCH * DS * DI];  // chunk prod(dA)
__device__ __align__(16) float g_part[(size_t)4 * MM * 128];     // split-K partials (GEMM2)

// fp16 activations, row-major M x K
__device__ __align__(16) __half g_xh [(size_t)MM * DM];
__device__ __align__(16) __half g_xvh[(size_t)MM * DI];       // conv+silu output (u)
__device__ __align__(16) __half g_dth[(size_t)MM * DTR];
__device__ __align__(16) __half g_ygh[(size_t)MM * DI];

// transposed fp16 weights, layout (N, K) row-major
__device__ __align__(16) __half g_winT[(size_t)(2*DI) * DM];
__device__ __align__(16) __half g_wxT[(size_t)128 * DI];      // rows 96..127 stay zero
__device__ __align__(16) __half g_wdtT[(size_t)DI * DTR];
__device__ __align__(16) __half g_woutT[(size_t)DM * DI];

// ===================== low-level helpers =====================
__device__ __forceinline__ uint32_t smem_u32(const void* p) {
    uint32_t a;
    asm("{ .reg .u64 t; cvta.to.shared.u64 t, %1; cvt.u32.u64 %0, t; }" : "=r"(a) : "l"(p));
    return a;
}
__device__ __forceinline__ void cpa16(uint32_t s, const void* g) {
    asm volatile("cp.async.cg.shared.global [%0], [%1], 16;" :: "r"(s), "l"(g));
}
#define CP_COMMIT() asm volatile("cp.async.commit_group;")
#define CP_WAIT(n)  asm volatile("cp.async.wait_group %0;" :: "n"(n))

__device__ __forceinline__ void ldsm4(uint32_t* r, uint32_t addr) {
    asm volatile("ldmatrix.sync.aligned.m8n8.x4.shared.b16 {%0,%1,%2,%3}, [%4];"
        : "=r"(r[0]), "=r"(r[1]), "=r"(r[2]), "=r"(r[3]) : "r"(addr));
}
__device__ __forceinline__ void mma16816(float* d, const uint32_t* a, const uint32_t* b) {
    asm volatile(
        "mma.sync.aligned.m16n8k16.row.col.f32.f16.f16.f32 "
        "{%0,%1,%2,%3}, {%4,%5,%6,%7}, {%8,%9}, {%0,%1,%2,%3};"
        : "+f"(d[0]), "+f"(d[1]), "+f"(d[2]), "+f"(d[3])
        : "r"(a[0]), "r"(a[1]), "r"(a[2]), "r"(a[3]), "r"(b[0]), "r"(b[1]));
}

// ================= HMMA GEMM: C(M,N) = A(M,K) @ B(N,K)^T, fp16 =================
// 128x128 CTA tile, BK=64, 8 warps (2M x 4N), warp tile 64x32.
// smem: 2 stages x (A 16KB + B 16KB) = 64KB -> 2 CTAs/SM.
#define ASZ 16384
#define STAGE 32768
#define HG_SMEM 65536

__global__ void __launch_bounds__(256, 2)
hgemm(const __half* __restrict__ A, const __half* __restrict__ B,
      float* __restrict__ C, int N, int K, int ldc,
      const float* __restrict__ bias, int epi, int kslice, size_t zstride)
{
    extern __shared__ char smem[];
    const uint32_t sb = smem_u32(smem);
    const int tid  = threadIdx.x;
    const int wid  = tid >> 5;
    const int lane = tid & 31;
    const int row0 = blockIdx.y * 128;
    const int col0 = blockIdx.x * 128;
    const int wm = wid & 1;     // 2 warps along M
    const int wn = wid >> 1;    // 4 warps along N

    const int kbase = blockIdx.z * kslice;
    C += (size_t)blockIdx.z * zstride;
    const int KT = kslice >> 6;

    float acc[4][4][4];
    #pragma unroll
    for (int i = 0; i < 4; i++)
        #pragma unroll
        for (int j = 0; j < 4; j++)
            #pragma unroll
            for (int q = 0; q < 4; q++) acc[i][j][q] = 0.0f;

    auto load_stage = [&](int s, int k0) {
        const uint32_t base = sb + (uint32_t)s * STAGE;
        #pragma unroll
        for (int i = 0; i < 4; i++) {
            const int lin = tid + i * 256;
            const int r = lin >> 3, c = lin & 7;
            const uint32_t so = (uint32_t)(r * 128 + ((c ^ (r & 7)) << 4));
            cpa16(base + so,       A + (size_t)(row0 + r) * K + k0 + c * 8);
            cpa16(base + ASZ + so, B + (size_t)(col0 + r) * K + k0 + c * 8);
        }
        CP_COMMIT();
    };

    auto compute_stage = [&](int s) {
        const uint32_t aBase = sb + (uint32_t)s * STAGE;
        const uint32_t bBase = aBase + ASZ;
        #pragma unroll
        for (int ks = 0; ks < 4; ks++) {
            uint32_t ah[4][4];
            #pragma unroll
            for (int mt = 0; mt < 4; mt++) {
                const int R = wm * 64 + mt * 16 + (lane & 15);
                const int c = ks * 2 + (lane >> 4);
                ldsm4(ah[mt], aBase + (uint32_t)(R * 128 + ((c ^ (R & 7)) << 4)));
            }
            #pragma unroll
            for (int g = 0; g < 2; g++) {
                const int R = wn * 32 + g * 16 + (lane & 7) + ((lane >> 4) & 1) * 8;
                const int c = ks * 2 + ((lane >> 3) & 1);
                uint32_t bh[4];
                ldsm4(bh, bBase + (uint32_t)(R * 128 + ((c ^ (R & 7)) << 4)));
                #pragma unroll
                for (int mt = 0; mt < 4; mt++)
                    #pragma unroll
                    for (int sub = 0; sub < 2; sub++)
                        mma16816(acc[mt][g * 2 + sub], ah[mt], &bh[sub * 2]);
            }
        }
    };

    load_stage(0, kbase);
    for (int kt = 0; kt < KT; kt++) {
        if (kt + 1 < KT) {
            load_stage((kt + 1) & 1, kbase + (kt + 1) * 64);
            CP_WAIT(1);
        } else {
            CP_WAIT(0);
        }
        __syncthreads();
        compute_stage(kt & 1);
        __syncthreads();
    }

    // ---- epilogue ----
    #pragma unroll
    for (int mt = 0; mt < 4; mt++) {
        const int row = row0 + wm * 64 + mt * 16 + (lane >> 2);
        #pragma unroll
        for (int j = 0; j < 4; j++) {
            const int col = col0 + wn * 32 + j * 8 + (lane & 3) * 2;
            float v0 = acc[mt][j][0], v1 = acc[mt][j][1];
            float v2 = acc[mt][j][2], v3 = acc[mt][j][3];
            if (epi == 1) {
                const float b0 = bias[col], b1 = bias[col + 1];
                v0 += b0; v0 = (v0 > 20.0f) ? v0 : log1pf(__expf(v0));
                v1 += b1; v1 = (v1 > 20.0f) ? v1 : log1pf(__expf(v1));
                v2 += b0; v2 = (v2 > 20.0f) ? v2 : log1pf(__expf(v2));
                v3 += b1; v3 = (v3 > 20.0f) ? v3 : log1pf(__expf(v3));
            }
            *(float2*)(C + (size_t)row * ldc + col)       = make_float2(v0, v1);
            *(float2*)(C + (size_t)(row + 8) * ldc + col) = make_float2(v2, v3);
        }
    }
}

// ---------------- split-K reduce for GEMM2 -> xdbl + fused dt fp16 ----------------
__global__ void __launch_bounds__(256)
reduce4(const float* __restrict__ part, float* __restrict__ xdbl, __half* __restrict__ dth)
{
    const int i = blockIdx.x * 256 + threadIdx.x;
    if (i >= MM * XDBL_W) return;
    const int r = i / XDBL_W, c = i - r * XDBL_W;
    const size_t o = (size_t)r * 128 + c;
    float s = part[o] + part[o + (size_t)MM * 128]
            + part[o + (size_t)2 * MM * 128] + part[o + (size_t)3 * MM * 128];
    xdbl[i] = s;
    if (c < DTR) dth[(size_t)r * DTR + c] = __float2half_rn(s);
}

// ---------------- weight transpose -> fp16: W(K,N) -> T(N,K) ----------------
__global__ void __launch_bounds__(256)
ttrans(const float* __restrict__ W, __half* __restrict__ T, int K, int N)
{
    __shared__ float t[32][33];
    const int n0 = blockIdx.x * 32;
    const int k0 = blockIdx.y * 32;
    const int tx = threadIdx.x & 31;
    const int ty = threadIdx.x >> 5;
    #pragma unroll
    for (int i = 0; i < 32; i += 8)
        t[ty + i][tx] = W[(size_t)(k0 + ty + i) * N + (n0 + tx)];
    __syncthreads();
    #pragma unroll
    for (int i = 0; i < 32; i += 8)
        T[(size_t)(n0 + ty + i) * K + (k0 + tx)] = __float2half_rn(t[tx][ty + i]);
}

// ---------------- fp32 -> fp16 (dense) ----------------
__global__ void __launch_bounds__(256)
to_half(const float* __restrict__ in, __half* __restrict__ h, int n4)
{
    const int i = blockIdx.x * blockDim.x + threadIdx.x;
    if (i >= n4) return;
    const float4 v = ((const float4*)in)[i];
    __half2 a = __floats2half2_rn(v.x, v.y);
    __half2 b = __floats2half2_rn(v.z, v.w);
    ((uint2*)h)[i] = make_uint2(*(uint32_t*)&a, *(uint32_t*)&b);
}

// ---------------- causal depthwise conv (k=4) + SiLU -> fp16 ----------------
__global__ void __launch_bounds__(256)
conv_silu_kernel(const float* __restrict__ xr, const float* __restrict__ w,
                 const float* __restrict__ bias, __half* __restrict__ oh)
{
    const int idx = blockIdx.x * blockDim.x + threadIdx.x;
    if (idx >= MM * DI) return;
    const int d = idx & (DI - 1);
    const int m = idx >> 11;
    const int l = m & (LL - 1);
    const int b = m >> 11;

    float acc = bias[d];
    #pragma unroll
    for (int i = 0; i < DC; i++) {
        const int lp = l + i - (DC - 1);
        if (lp >= 0)
            acc = fmaf(xr[((size_t)(b * LL + lp)) * (2 * DI) + d], w[d * DC + i], acc);
    }
    const float v = acc * (1.0f / (1.0f + __expf(-acc)));
    oh[idx] = __float2half_rn(v);
}

// ---------------- chunked selective scan: pass 1 (chunk-local h and prod dA) ----------------
__global__ void __launch_bounds__(256)
scan_p1(const float* __restrict__ dt, const __half* __restrict__ u,
        const float* __restrict__ xdbl, const float* __restrict__ logA,
        float* __restrict__ H, float* __restrict__ P)
{
    const int idx = blockIdx.x * 256 + threadIdx.x;      // 65536
    const int d = idx & (DI - 1);
    const int t = idx >> 11;
    const int c = t & (NCH - 1);
    const int b = t >> 3;

    float A[DS];
    #pragma unroll
    for (int n = 0; n < DS; n++) A[n] = -__expf(logA[d * DS + n]);
    const float A0 = A[0];
    bool pw = true;
    #pragma unroll
    for (int n = 1; n < DS; n++)
        pw = pw && (fabsf(A[n] - (float)(n + 1) * A0) <= 1e-5f * fabsf(A[n]));

    float h[DS], Pr[DS];
    #pragma unroll
    for (int n = 0; n < DS; n++) { h[n] = 0.0f; Pr[n] = 1.0f; }

    const int l0 = c * CL;
    for (int l = l0; l < l0 + CL; l++) {
        const size_t m = (size_t)b * LL + l;
        const float dtv = dt[m * DI + d];
        const float uv  = __half2float(u[m * DI + d]);
        const float dtu = dtv * uv;

        float e[DS];
        if (pw) {
            const float e1 = __expf(dtv * A0);
            float p = e1;
            e[0] = p;
            #pragma unroll
            for (int n = 1; n < DS; n++) { p *= e1; e[n] = p; }
        } else {
            #pragma unroll
            for (int n = 0; n < DS; n++) e[n] = __expf(dtv * A[n]);
        }

        const float4* bp = (const float4*)(xdbl + m * XDBL_W + DTR);
        float Bv[DS];
        #pragma unroll
        for (int q = 0; q < 4; q++) {
            const float4 v = bp[q];
            Bv[q*4+0]=v.x; Bv[q*4+1]=v.y; Bv[q*4+2]=v.z; Bv[q*4+3]=v.w;
        }
        #pragma unroll
        for (int n = 0; n < DS; n++) {
            h[n] = fmaf(e[n], h[n], dtu * Bv[n]);
            Pr[n] *= e[n];
        }
    }
    const size_t o = ((size_t)(b * NCH + c) * DS) * DI + d;
    #pragma unroll
    for (int n = 0; n < DS; n++) { H[o + (size_t)n * DI] = h[n]; P[o + (size_t)n * DI] = Pr[n]; }
}

// ---------------- chunked scan: pass 2 (recombine + y + gate -> fp16) ----------------
__global__ void __launch_bounds__(256)
scan_p2(const float* __restrict__ dt, const __half* __restrict__ u,
        const float* __restrict__ xdbl, const float* __restrict__ logA,
        const float* __restrict__ Dp, const float* __restrict__ xr,
        const float* __restrict__ H, const float* __restrict__ P,
        __half* __restrict__ ygh)
{
    const int idx = blockIdx.x * 256 + threadIdx.x;
    const int d = idx & (DI - 1);
    const int t = idx >> 11;
    const int c = t & (NCH - 1);
    const int b = t >> 3;

    float A[DS];
    #pragma unroll
    for (int n = 0; n < DS; n++) A[n] = -__expf(logA[d * DS + n]);
    const float A0 = A[0];
    bool pw = true;
    #pragma unroll
    for (int n = 1; n < DS; n++)
        pw = pw && (fabsf(A[n] - (float)(n + 1) * A0) <= 1e-5f * fabsf(A[n]));

    // recombine preceding chunk states
    float h[DS];
    #pragma unroll
    for (int n = 0; n < DS; n++) h[n] = 0.0f;
    for (int j = 0; j < c; j++) {
        const size_t o = ((size_t)(b * NCH + j) * DS) * DI + d;
        #pragma unroll
        for (int n = 0; n < DS; n++)
            h[n] = fmaf(P[o + (size_t)n * DI], h[n], H[o + (size_t)n * DI]);
    }
    const float Dv = Dp[d];

    const int l0 = c * CL;
    for (int l = l0; l < l0 + CL; l++) {
        const size_t m = (size_t)b * LL + l;
        const float dtv = dt[m * DI + d];
        const float uv  = __half2float(u[m * DI + d]);
        const float dtu = dtv * uv;

        float e[DS];
        if (pw) {
            const float e1 = __expf(dtv * A0);
            float p = e1;
            e[0] = p;
            #pragma unroll
            for (int n = 1; n < DS; n++) { p *= e1; e[n] = p; }
        } else {
            #pragma unroll
            for (int n = 0; n < DS; n++) e[n] = __expf(dtv * A[n]);
        }

        const float4* bp = (const float4*)(xdbl + m * XDBL_W + DTR);
        float Bv[DS], Cv[DS];
        #pragma unroll
        for (int q = 0; q < 4; q++) {
            const float4 v = bp[q];
            Bv[q*4+0]=v.x; Bv[q*4+1]=v.y; Bv[q*4+2]=v.z; Bv[q*4+3]=v.w;
        }
        #pragma unroll
        for (int q = 0; q < 4; q++) {
            const float4 v = bp[4 + q];
            Cv[q*4+0]=v.x; Cv[q*4+1]=v.y; Cv[q*4+2]=v.z; Cv[q*4+3]=v.w;
        }

        float y = 0.0f;
        #pragma unroll
        for (int n = 0; n < DS; n++) {
            h[n] = fmaf(e[n], h[n], dtu * Bv[n]);
            y = fmaf(Cv[n], h[n], y);
        }
        y = fmaf(Dv, uv, y);

        const float r = xr[m * (2 * DI) + DI + d];
        const float g = r * (1.0f / (1.0f + __expf(-r)));
        ygh[m * DI + d] = __float2half_rn(y * g);
    }
}

// ---------------- host launcher ----------------
extern "C" void kernel_launch(void* const* d_in, const int* in_sizes, int n_in,
                              void* d_out, int out_size)
{
    const float* x      = (const float*)d_in[0];
    const float* W_in   = (const float*)d_in[1];
    const float* conv_w = (const float*)d_in[2];
    const float* conv_b = (const float*)d_in[3];
    const float* W_x    = (const float*)d_in[4];
    const float* W_dt   = (const float*)d_in[5];
    const float* b_dt   = (const float*)d_in[6];
    const float* logA   = (const float*)d_in[7];
    const float* Dp     = (const float*)d_in[8];
    const float* W_out  = (const float*)d_in[9];
    float* out = (float*)d_out;

    cudaFuncSetAttribute(hgemm, cudaFuncAttributeMaxDynamicSharedMemorySize, HG_SMEM);

    float *xr, *xdbl, *dtb, *Hb, *Pb, *part;
    cudaGetSymbolAddress((void**)&xr,   g_xr);
    cudaGetSymbolAddress((void**)&xdbl, g_xdbl);
    cudaGetSymbolAddress((void**)&dtb,  g_dt);
    cudaGetSymbolAddress((void**)&Hb,   g_H);
    cudaGetSymbolAddress((void**)&Pb,   g_P);
    cudaGetSymbolAddress((void**)&part, g_part);

    __half *xh, *xvh, *dth, *ygh;
    cudaGetSymbolAddress((void**)&xh,  g_xh);
    cudaGetSymbolAddress((void**)&xvh, g_xvh);
    cudaGetSymbolAddress((void**)&dth, g_dth);
    cudaGetSymbolAddress((void**)&ygh, g_ygh);

    __half *winT, *wxT, *wdtT, *woutT;
    cudaGetSymbolAddress((void**)&winT,  g_winT);
    cudaGetSymbolAddress((void**)&wxT,   g_wxT);
    cudaGetSymbolAddress((void**)&wdtT,  g_wdtT);
    cudaGetSymbolAddress((void**)&woutT, g_woutT);

    // weight prep: transpose -> fp16
    ttrans<<<dim3((2*DI)/32, DM/32), 256>>>(W_in, winT, DM, 2*DI);
    ttrans<<<dim3(XDBL_W/32, DI/32), 256>>>(W_x, wxT, DI, XDBL_W);
    ttrans<<<dim3(DI/32, DTR/32), 256>>>(W_dt, wdtT, DTR, DI);
    ttrans<<<dim3(DM/32, DI/32), 256>>>(W_out, woutT, DI, DM);

    // x -> fp16
    to_half<<<(MM*DM/4 + 255)/256, 256>>>(x, xh, MM*DM/4);

    // 1) x @ W_in -> xr (8192 x 4096)   [grid 32x64]
    hgemm<<<dim3((2*DI)/128, MM/128), 256, HG_SMEM>>>(
        xh, winT, xr, 2*DI, DM, 2*DI, nullptr, 0, DM, 0);

    // 2) causal conv + silu -> xvh (fp16)
    conv_silu_kernel<<<(MM*DI + 255)/256, 256>>>(xr, conv_w, conv_b, xvh);

    // 3) xval @ W_x -> partials (split-K=4), then reduce -> xdbl + dt fp16
    hgemm<<<dim3(1, MM/128, 4), 256, HG_SMEM>>>(
        xvh, wxT, part, 128, DI, 128, nullptr, 0, DI/4, (size_t)MM*128);
    reduce4<<<(MM*XDBL_W + 255)/256, 256>>>(part, xdbl, dth);

    // 4) softplus(dt_in @ W_dt + b_dt) -> dt (8192 x 2048), K=64
    hgemm<<<dim3(DI/128, MM/128), 256, HG_SMEM>>>(
        dth, wdtT, dtb, DI, DTR, DI, b_dt, 1, DTR, 0);

    // 5) chunked selective scan
    scan_p1<<<(BB*DI*NCH)/256, 256>>>(dtb, xvh, xdbl, logA, Hb, Pb);
    scan_p2<<<(BB*DI*NCH)/256, 256>>>(dtb, xvh, xdbl, logA, Dp, xr, Hb, Pb, ygh);

    // 6) yg @ W_out -> out (8192 x 1024)
    hgemm<<<dim3(DM/128, MM/128), 256, HG_SMEM>>>(
        ygh, woutT, out, DM, DI, DM, nullptr, 0, DI, 0);
}